// round 2
// baseline (speedup 1.0000x reference)
#include <cuda_runtime.h>
#include <cuda_bf16.h>
#include <cstddef>

#define N_NODESC 100000
#define N_EDGESC 3200000
#define N_GRAPHSC 2048
#define DIM 256
#define EPSC 1e-5f

// ---------------- scratch (static device globals; no allocation) ----------------
__device__ float g_h[(size_t)N_NODESC * DIM];        // node features (ping)
__device__ float g_z[(size_t)N_NODESC * DIM];        // aggregation buffer
__device__ float g_y[(size_t)N_NODESC * 2 * DIM];    // hidden (up to 512 wide)
__device__ float g_sum[512];
__device__ float g_sq[512];
__device__ float g_scale[512];
__device__ float g_shift[512];

// ---------------- atom encoder: h[n,f] = sum_c atom_emb[c, x[n,c], f] ----------------
__global__ void atom_encode(const int* __restrict__ x, const float* __restrict__ emb) {
    int n = blockIdx.x;
    __shared__ int xi[9];
    if (threadIdx.x < 9) xi[threadIdx.x] = x[n * 9 + threadIdx.x];
    __syncthreads();
    int f = threadIdx.x;
    float s = 0.f;
#pragma unroll
    for (int c = 0; c < 9; c++) s += emb[((size_t)(c * 100 + xi[c])) * DIM + f];
    g_h[(size_t)n * DIM + f] = s;
}

// ---------------- copy h -> z (init aggregation with self term) ----------------
__global__ void copy_h_to_z() {
    size_t i = (size_t)blockIdx.x * blockDim.x + threadIdx.x;  // float4 index
    ((float4*)g_z)[i] = ((const float4*)g_h)[i];
}

// ---------------- edge message passing: z[dst] += relu(h[src] + bond_emb(edge)) ----------------
__global__ void edge_mp(const int* __restrict__ ei, const int* __restrict__ ea,
                        const float* __restrict__ bemb) {
    int e = (int)(((size_t)blockIdx.x * blockDim.x + threadIdx.x) >> 5);
    if (e >= N_EDGESC) return;
    int lane = threadIdx.x & 31;
    int src = __ldg(ei + e);
    int dst = __ldg(ei + N_EDGESC + e);
    int a0 = __ldg(ea + (size_t)e * 3 + 0);
    int a1 = __ldg(ea + (size_t)e * 3 + 1);
    int a2 = __ldg(ea + (size_t)e * 3 + 2);
    const float* hs = g_h + (size_t)src * DIM;
    float*       zd = g_z + (size_t)dst * DIM;
    const float* t0 = bemb + (size_t)(0 * 10 + a0) * DIM;
    const float* t1 = bemb + (size_t)(1 * 10 + a1) * DIM;
    const float* t2 = bemb + (size_t)(2 * 10 + a2) * DIM;
#pragma unroll
    for (int i = 0; i < 2; i++) {
        int f = (lane + i * 32) * 4;
        float4 h4 = *(const float4*)(hs + f);
        float4 e0 = *(const float4*)(t0 + f);
        float4 e1 = *(const float4*)(t1 + f);
        float4 e2 = *(const float4*)(t2 + f);
        float m0 = fmaxf(h4.x + e0.x + e1.x + e2.x, 0.f);
        float m1 = fmaxf(h4.y + e0.y + e1.y + e2.y, 0.f);
        float m2 = fmaxf(h4.z + e0.z + e1.z + e2.z, 0.f);
        float m3 = fmaxf(h4.w + e0.w + e1.w + e2.w, 0.f);
        atomicAdd(zd + f + 0, m0);
        atomicAdd(zd + f + 1, m1);
        atomicAdd(zd + f + 2, m2);
        atomicAdd(zd + f + 3, m3);
    }
}

// ---------------- stats helpers ----------------
__global__ void zero_stats() {
    int t = blockIdx.x * blockDim.x + threadIdx.x;
    if (t < 512) { g_sum[t] = 0.f; g_sq[t] = 0.f; }
}

__global__ void colstats(const float* __restrict__ Y, int M, int Dh) {
    int col = blockIdx.x * 256 + threadIdx.x;
    int r0 = blockIdx.y * 2048;
    int r1 = min(r0 + 2048, M);
    float s = 0.f, sq = 0.f;
    for (int r = r0; r < r1; r++) {
        float v = Y[(size_t)r * Dh + col];
        s += v;
        sq += v * v;
    }
    atomicAdd(&g_sum[col], s);
    atomicAdd(&g_sq[col], sq);
}

__global__ void finstats(const float* __restrict__ gamma, const float* __restrict__ beta, int Dh) {
    int c = blockIdx.x * 256 + threadIdx.x;
    if (c >= Dh) return;
    float inv_n = 1.0f / (float)N_NODESC;
    float mu = g_sum[c] * inv_n;
    float var = g_sq[c] * inv_n - mu * mu;
    float rs = rsqrtf(var + EPSC);
    float sc = rs * gamma[c];
    g_scale[c] = sc;
    g_shift[c] = beta[c] - mu * sc;
}

// ---------------- SGEMM: C[M,Nc] = op(A[M,K]) @ B[K,Nc] + bias ----------------
// TRANSFORM: A element a -> relu(a*scale[k] + shift[k])  (fused BN+ReLU of hidden)
// RELU: relu on output
template <bool TRANSFORM, bool RELU>
__global__ __launch_bounds__(256) void gemm_kernel(
    const float* __restrict__ A, const float* __restrict__ B,
    const float* __restrict__ bias, float* __restrict__ C,
    int M, int K, int Nc) {
    const int BM = 64, BN = 64, BK = 16;
    __shared__ float As[BK][BM];
    __shared__ float Bs[BK][BN];
    int tid = threadIdx.x;
    int bm = blockIdx.y * BM;
    int bn = blockIdx.x * BN;
    int ty = tid >> 4;        // 0..15
    int tx = tid & 15;        // 0..15

    int am = tid >> 2;        // A-load row within tile (0..63)
    int ak = (tid & 3) * 4;   // A-load k offset (0,4,8,12)
    int bk = tid >> 4;        // B-load k row (0..15)
    int bq = (tid & 15) * 4;  // B-load col offset (0..60)

    bool arow_ok = (bm + am) < M;
    float acc[4][4] = {};

    for (int k0 = 0; k0 < K; k0 += BK) {
        float4 a4 = make_float4(0.f, 0.f, 0.f, 0.f);
        if (arow_ok) a4 = *(const float4*)(A + (size_t)(bm + am) * K + k0 + ak);
        if (TRANSFORM) {
            a4.x = fmaxf(a4.x * g_scale[k0 + ak + 0] + g_shift[k0 + ak + 0], 0.f);
            a4.y = fmaxf(a4.y * g_scale[k0 + ak + 1] + g_shift[k0 + ak + 1], 0.f);
            a4.z = fmaxf(a4.z * g_scale[k0 + ak + 2] + g_shift[k0 + ak + 2], 0.f);
            a4.w = fmaxf(a4.w * g_scale[k0 + ak + 3] + g_shift[k0 + ak + 3], 0.f);
        }
        As[ak + 0][am] = a4.x;
        As[ak + 1][am] = a4.y;
        As[ak + 2][am] = a4.z;
        As[ak + 3][am] = a4.w;

        float4 b4 = *(const float4*)(B + (size_t)(k0 + bk) * Nc + bn + bq);
        *(float4*)&Bs[bk][bq] = b4;
        __syncthreads();

#pragma unroll
        for (int k = 0; k < BK; k++) {
            float a[4], b[4];
#pragma unroll
            for (int i = 0; i < 4; i++) a[i] = As[k][ty * 4 + i];
#pragma unroll
            for (int j = 0; j < 4; j++) b[j] = Bs[k][tx * 4 + j];
#pragma unroll
            for (int i = 0; i < 4; i++)
#pragma unroll
                for (int j = 0; j < 4; j++) acc[i][j] = fmaf(a[i], b[j], acc[i][j]);
        }
        __syncthreads();
    }

#pragma unroll
    for (int i = 0; i < 4; i++) {
        int r = bm + ty * 4 + i;
        if (r >= M) break;
#pragma unroll
        for (int j = 0; j < 4; j++) {
            int c = bn + tx * 4 + j;
            float v = acc[i][j] + bias[c];
            if (RELU) v = fmaxf(v, 0.f);
            C[(size_t)r * Nc + c] = v;
        }
    }
}

// ---------------- global add pool ----------------
__global__ void zero_out(float* __restrict__ out) {
    int i = blockIdx.x * blockDim.x + threadIdx.x;
    if (i < N_GRAPHSC * DIM) out[i] = 0.f;
}

__global__ void pool_kernel(const int* __restrict__ batch, float* __restrict__ out) {
    int n = (int)(((size_t)blockIdx.x * blockDim.x + threadIdx.x) >> 5);
    if (n >= N_NODESC) return;
    int lane = threadIdx.x & 31;
    int gidx = __ldg(batch + n);
    const float* h = g_h + (size_t)n * DIM;
    float* o = out + (size_t)gidx * DIM;
#pragma unroll
    for (int i = 0; i < 8; i++) {
        int f = lane + i * 32;
        atomicAdd(o + f, h[f]);
    }
}

// ---------------- launch ----------------
extern "C" void kernel_launch(void* const* d_in, const int* in_sizes, int n_in,
                              void* d_out, int out_size) {
    const int* x      = (const int*)d_in[0];
    const int* ei     = (const int*)d_in[1];
    const int* ea     = (const int*)d_in[2];
    const int* batch  = (const int*)d_in[3];
    const float* atom = (const float*)d_in[4];
    const float* be1  = (const float*)d_in[5];
    const float* be2  = (const float*)d_in[6];
    const float* c1_w1 = (const float*)d_in[7];
    const float* c1_b1 = (const float*)d_in[8];
    const float* c1_g  = (const float*)d_in[9];
    const float* c1_be = (const float*)d_in[10];
    const float* c1_w2 = (const float*)d_in[11];
    const float* c1_b2 = (const float*)d_in[12];
    const float* c2_w1 = (const float*)d_in[13];
    const float* c2_b1 = (const float*)d_in[14];
    const float* c2_g  = (const float*)d_in[15];
    const float* c2_be = (const float*)d_in[16];
    const float* c2_w2 = (const float*)d_in[17];
    const float* c2_b2 = (const float*)d_in[18];
    float* out = (float*)d_out;

    // CRITICAL: resolve true device addresses of the __device__ globals.
    // Referencing g_h/g_z/g_y directly in host code passes the HOST shadow
    // address (and GB300's ATS coherence makes the GPU silently read/write
    // host .bss instead of faulting). cudaGetSymbolAddress is not a stream
    // op and not an allocation -> graph-capture safe.
    float *hz, *zz, *yz;
    cudaGetSymbolAddress((void**)&hz, g_h);
    cudaGetSymbolAddress((void**)&zz, g_z);
    cudaGetSymbolAddress((void**)&yz, g_y);

    const int M = N_NODESC;
    const int copy_blocks = (int)(((size_t)N_NODESC * DIM / 4) / 256);
    const int edge_blocks = (N_EDGESC * 32 + 255) / 256;
    dim3 g1(512 / 64, (M + 63) / 64);   // K=256 -> Nc=512
    dim3 g2(256 / 64, (M + 63) / 64);   // Nc=256
    const int statrows = (M + 2047) / 2048;

    // atom encoder
    atom_encode<<<N_NODESC, 256>>>(x, atom);

    // ---- conv1 ----
    copy_h_to_z<<<copy_blocks, 256>>>();
    edge_mp<<<edge_blocks, 256>>>(ei, ea, be1);
    zero_stats<<<2, 256>>>();
    gemm_kernel<false, false><<<g1, 256>>>(zz, c1_w1, c1_b1, yz, M, 256, 512);
    colstats<<<dim3(2, statrows), 256>>>(yz, M, 512);
    finstats<<<2, 256>>>(c1_g, c1_be, 512);
    gemm_kernel<true, true><<<g2, 256>>>(yz, c1_w2, c1_b2, hz, M, 512, 256);

    // ---- conv2 ----
    copy_h_to_z<<<copy_blocks, 256>>>();
    edge_mp<<<edge_blocks, 256>>>(ei, ea, be2);
    zero_stats<<<2, 256>>>();
    gemm_kernel<false, false><<<g2, 256>>>(zz, c2_w1, c2_b1, yz, M, 256, 256);
    colstats<<<dim3(1, statrows), 256>>>(yz, M, 256);
    finstats<<<1, 256>>>(c2_g, c2_be, 256);
    gemm_kernel<true, true><<<g2, 256>>>(yz, c2_w2, c2_b2, hz, M, 256, 256);

    // ---- global add pool ----
    zero_out<<<(N_GRAPHSC * DIM + 255) / 256, 256>>>(out);
    pool_kernel<<<(N_NODESC * 32 + 255) / 256, 256>>>(batch, out);
}

// round 3
// speedup vs baseline: 1.5897x; 1.5897x over previous
#include <cuda_runtime.h>
#include <cuda_bf16.h>
#include <cstddef>

#define N_NODESC 100000
#define N_EDGESC 3200000
#define N_GRAPHSC 2048
#define DIM 256
#define EPSC 1e-5f

// ---------------- scratch (static device globals; no allocation) ----------------
__device__ float g_h[(size_t)N_NODESC * DIM];
__device__ float g_z[(size_t)N_NODESC * DIM];
__device__ float g_y[(size_t)N_NODESC * 2 * DIM];
__device__ float g_sum[512];
__device__ float g_sq[512];
__device__ float g_scale[512];
__device__ float g_shift[512];

// vectorized no-return global f32x4 add reduction (sm_90+)
__device__ __forceinline__ void red_v4(float* addr, float a, float b, float c, float d) {
    asm volatile("red.global.add.v4.f32 [%0], {%1,%2,%3,%4};"
                 :: "l"(addr), "f"(a), "f"(b), "f"(c), "f"(d) : "memory");
}

// ---------------- atom encoder ----------------
__global__ void atom_encode(const int* __restrict__ x, const float* __restrict__ emb) {
    int n = blockIdx.x;
    __shared__ int xi[9];
    if (threadIdx.x < 9) xi[threadIdx.x] = x[n * 9 + threadIdx.x];
    __syncthreads();
    int f = threadIdx.x;
    float s = 0.f;
#pragma unroll
    for (int c = 0; c < 9; c++) s += emb[((size_t)(c * 100 + xi[c])) * DIM + f];
    g_h[(size_t)n * DIM + f] = s;
}

// ---------------- copy h -> z ----------------
__global__ void copy_h_to_z() {
    size_t i = (size_t)blockIdx.x * blockDim.x + threadIdx.x;
    ((float4*)g_z)[i] = ((const float4*)g_h)[i];
}

// ---------------- edge message passing ----------------
__global__ void edge_mp(const int* __restrict__ ei, const int* __restrict__ ea,
                        const float* __restrict__ bemb) {
    int e = (int)(((size_t)blockIdx.x * blockDim.x + threadIdx.x) >> 5);
    if (e >= N_EDGESC) return;
    int lane = threadIdx.x & 31;
    int src = __ldg(ei + e);
    int dst = __ldg(ei + N_EDGESC + e);
    int a0 = __ldg(ea + (size_t)e * 3 + 0);
    int a1 = __ldg(ea + (size_t)e * 3 + 1);
    int a2 = __ldg(ea + (size_t)e * 3 + 2);
    const float* hs = g_h + (size_t)src * DIM;
    float*       zd = g_z + (size_t)dst * DIM;
    const float* t0 = bemb + (size_t)(0 * 10 + a0) * DIM;
    const float* t1 = bemb + (size_t)(1 * 10 + a1) * DIM;
    const float* t2 = bemb + (size_t)(2 * 10 + a2) * DIM;
#pragma unroll
    for (int i = 0; i < 2; i++) {
        int f = (lane + i * 32) * 4;
        float4 h4 = *(const float4*)(hs + f);
        float4 e0 = *(const float4*)(t0 + f);
        float4 e1 = *(const float4*)(t1 + f);
        float4 e2 = *(const float4*)(t2 + f);
        float m0 = fmaxf(h4.x + e0.x + e1.x + e2.x, 0.f);
        float m1 = fmaxf(h4.y + e0.y + e1.y + e2.y, 0.f);
        float m2 = fmaxf(h4.z + e0.z + e1.z + e2.z, 0.f);
        float m3 = fmaxf(h4.w + e0.w + e1.w + e2.w, 0.f);
        red_v4(zd + f, m0, m1, m2, m3);
    }
}

// ---------------- stats ----------------
__global__ void zero_stats() {
    int t = blockIdx.x * blockDim.x + threadIdx.x;
    if (t < 512) { g_sum[t] = 0.f; g_sq[t] = 0.f; }
}

__global__ void finstats(const float* __restrict__ gamma, const float* __restrict__ beta, int Dh) {
    int c = blockIdx.x * 256 + threadIdx.x;
    if (c >= Dh) return;
    float inv_n = 1.0f / (float)N_NODESC;
    float mu = g_sum[c] * inv_n;
    float var = g_sq[c] * inv_n - mu * mu;
    float rs = rsqrtf(var + EPSC);
    float sc = rs * gamma[c];
    g_scale[c] = sc;
    g_shift[c] = beta[c] - mu * sc;
}

// ---------------- SGEMM 128x128x8, 8x8 per thread (4+4 split layout) ----------------
// TRANSFORM: A elem -> relu(a*scale[k]+shift[k]); RELU: relu output; STATS: col sums of output
template <bool TRANSFORM, bool RELU, bool STATS>
__global__ __launch_bounds__(256) void gemm128(
    const float* __restrict__ A, const float* __restrict__ B,
    const float* __restrict__ bias, float* __restrict__ C,
    int M, int K, int Nc) {
    const int BM = 128, BN = 128, BK = 8;
    __shared__ float As[BK][BM];
    __shared__ float Bs[BK][BN];
    int tid = threadIdx.x;
    int bm = blockIdx.y * BM;
    int bn = blockIdx.x * BN;

    int arow = tid >> 1;          // 0..127
    int akq  = (tid & 1) * 4;     // 0 or 4
    int brow = tid >> 5;          // 0..7
    int bcol = (tid & 31) * 4;    // 0..124

    int ty = tid >> 4;            // 0..15
    int tx = tid & 15;            // 0..15

    bool arow_ok = (bm + arow) < M;
    const float* aptr = A + (size_t)(bm + arow) * K + akq;

    float acc[8][8];
#pragma unroll
    for (int i = 0; i < 8; i++)
#pragma unroll
        for (int j = 0; j < 8; j++) acc[i][j] = 0.f;

    for (int k0 = 0; k0 < K; k0 += BK) {
        float4 a4 = make_float4(0.f, 0.f, 0.f, 0.f);
        if (arow_ok) a4 = *(const float4*)(aptr + k0);
        if (TRANSFORM) {
            int kb = k0 + akq;
            a4.x = fmaxf(a4.x * g_scale[kb + 0] + g_shift[kb + 0], 0.f);
            a4.y = fmaxf(a4.y * g_scale[kb + 1] + g_shift[kb + 1], 0.f);
            a4.z = fmaxf(a4.z * g_scale[kb + 2] + g_shift[kb + 2], 0.f);
            a4.w = fmaxf(a4.w * g_scale[kb + 3] + g_shift[kb + 3], 0.f);
        }
        As[akq + 0][arow] = a4.x;
        As[akq + 1][arow] = a4.y;
        As[akq + 2][arow] = a4.z;
        As[akq + 3][arow] = a4.w;

        *(float4*)&Bs[brow][bcol] = *(const float4*)(B + (size_t)(k0 + brow) * Nc + bn + bcol);
        __syncthreads();

#pragma unroll
        for (int k = 0; k < BK; k++) {
            float a[8], b[8];
            *(float4*)&a[0] = *(const float4*)&As[k][ty * 4];
            *(float4*)&a[4] = *(const float4*)&As[k][64 + ty * 4];
            *(float4*)&b[0] = *(const float4*)&Bs[k][tx * 4];
            *(float4*)&b[4] = *(const float4*)&Bs[k][64 + tx * 4];
#pragma unroll
            for (int i = 0; i < 8; i++)
#pragma unroll
                for (int j = 0; j < 8; j++) acc[i][j] = fmaf(a[i], b[j], acc[i][j]);
        }
        __syncthreads();
    }

    // epilogue
    float4 bias_lo, bias_hi;
    bias_lo = *(const float4*)(bias + bn + tx * 4);
    bias_hi = *(const float4*)(bias + bn + 64 + tx * 4);
    float bb[8] = {bias_lo.x, bias_lo.y, bias_lo.z, bias_lo.w,
                   bias_hi.x, bias_hi.y, bias_hi.z, bias_hi.w};

    float s[8], q[8];
#pragma unroll
    for (int j = 0; j < 8; j++) { s[j] = 0.f; q[j] = 0.f; }

#pragma unroll
    for (int i = 0; i < 8; i++) {
        int r = bm + ((i < 4) ? (ty * 4 + i) : (64 + ty * 4 + i - 4));
        if (r >= M) continue;
        float v[8];
#pragma unroll
        for (int j = 0; j < 8; j++) {
            v[j] = acc[i][j] + bb[j];
            if (RELU) v[j] = fmaxf(v[j], 0.f);
            if (STATS) { s[j] += v[j]; q[j] += v[j] * v[j]; }
        }
        float* crow = C + (size_t)r * Nc + bn;
        *(float4*)(crow + tx * 4)      = make_float4(v[0], v[1], v[2], v[3]);
        *(float4*)(crow + 64 + tx * 4) = make_float4(v[4], v[5], v[6], v[7]);
    }

    if (STATS) {
#pragma unroll
        for (int j = 0; j < 8; j++) {
            int c = bn + ((j < 4) ? (tx * 4 + j) : (64 + tx * 4 + j - 4 - (tx * 4 + j - 4)) );
            // recompute column properly below
        }
        // columns: j<4 -> bn+tx*4+j ; j>=4 -> bn+64+tx*4+(j-4)
#pragma unroll
        for (int j = 0; j < 8; j++) {
            int c = bn + ((j < 4) ? (tx * 4 + j) : (64 + tx * 4 + (j - 4)));
            atomicAdd(&g_sum[c], s[j]);
            atomicAdd(&g_sq[c], q[j]);
        }
    }
}

// ---------------- global add pool ----------------
__global__ void zero_out(float* __restrict__ out) {
    int i = blockIdx.x * blockDim.x + threadIdx.x;
    if (i < N_GRAPHSC * DIM / 4) {
        ((float4*)out)[i] = make_float4(0.f, 0.f, 0.f, 0.f);
    }
}

__global__ void pool_kernel(const int* __restrict__ batch, float* __restrict__ out) {
    int n = (int)(((size_t)blockIdx.x * blockDim.x + threadIdx.x) >> 5);
    if (n >= N_NODESC) return;
    int lane = threadIdx.x & 31;
    int gidx = __ldg(batch + n);
    const float* h = g_h + (size_t)n * DIM;
    float* o = out + (size_t)gidx * DIM;
#pragma unroll
    for (int i = 0; i < 2; i++) {
        int f = (lane + i * 32) * 4;
        float4 v = *(const float4*)(h + f);
        red_v4(o + f, v.x, v.y, v.z, v.w);
    }
}

// ---------------- launch ----------------
extern "C" void kernel_launch(void* const* d_in, const int* in_sizes, int n_in,
                              void* d_out, int out_size) {
    const int* x      = (const int*)d_in[0];
    const int* ei     = (const int*)d_in[1];
    const int* ea     = (const int*)d_in[2];
    const int* batch  = (const int*)d_in[3];
    const float* atom = (const float*)d_in[4];
    const float* be1  = (const float*)d_in[5];
    const float* be2  = (const float*)d_in[6];
    const float* c1_w1 = (const float*)d_in[7];
    const float* c1_b1 = (const float*)d_in[8];
    const float* c1_g  = (const float*)d_in[9];
    const float* c1_be = (const float*)d_in[10];
    const float* c1_w2 = (const float*)d_in[11];
    const float* c1_b2 = (const float*)d_in[12];
    const float* c2_w1 = (const float*)d_in[13];
    const float* c2_b1 = (const float*)d_in[14];
    const float* c2_g  = (const float*)d_in[15];
    const float* c2_be = (const float*)d_in[16];
    const float* c2_w2 = (const float*)d_in[17];
    const float* c2_b2 = (const float*)d_in[18];
    float* out = (float*)d_out;

    float *hz, *zz, *yz;
    cudaGetSymbolAddress((void**)&hz, g_h);
    cudaGetSymbolAddress((void**)&zz, g_z);
    cudaGetSymbolAddress((void**)&yz, g_y);

    const int M = N_NODESC;
    const int copy_blocks = (int)(((size_t)N_NODESC * DIM / 4) / 256);
    const int edge_blocks = (N_EDGESC * 32 + 255) / 256;
    const int mtiles = (M + 127) / 128;
    dim3 gA(512 / 128, mtiles);   // Nc=512
    dim3 gB(256 / 128, mtiles);   // Nc=256

    atom_encode<<<N_NODESC, 256>>>(x, atom);

    // ---- conv1 ----
    copy_h_to_z<<<copy_blocks, 256>>>();
    edge_mp<<<edge_blocks, 256>>>(ei, ea, be1);
    zero_stats<<<2, 256>>>();
    gemm128<false, false, true><<<gA, 256>>>(zz, c1_w1, c1_b1, yz, M, 256, 512);
    finstats<<<2, 256>>>(c1_g, c1_be, 512);
    gemm128<true, true, false><<<gB, 256>>>(yz, c1_w2, c1_b2, hz, M, 512, 256);

    // ---- conv2 ----
    copy_h_to_z<<<copy_blocks, 256>>>();
    edge_mp<<<edge_blocks, 256>>>(ei, ea, be2);
    zero_stats<<<2, 256>>>();
    gemm128<false, false, true><<<gB, 256>>>(zz, c2_w1, c2_b1, yz, M, 256, 256);
    finstats<<<1, 256>>>(c2_g, c2_be, 256);
    gemm128<true, true, false><<<gB, 256>>>(yz, c2_w2, c2_b2, hz, M, 256, 256);

    // ---- pool ----
    zero_out<<<(N_GRAPHSC * DIM / 4 + 255) / 256, 256>>>(out);
    pool_kernel<<<(N_NODESC * 32 + 255) / 256, 256>>>(batch, out);
}

// round 4
// speedup vs baseline: 1.6556x; 1.0415x over previous
#include <cuda_runtime.h>
#include <cuda_bf16.h>
#include <cstddef>

#define N_NODESC 100000
#define N_EDGESC 3200000
#define N_GRAPHSC 2048
#define DIM 256
#define EPSC 1e-5f

// ---------------- scratch ----------------
__device__ float g_h[(size_t)N_NODESC * DIM];
__device__ float g_z[(size_t)N_NODESC * DIM];
__device__ float g_y[(size_t)N_NODESC * 2 * DIM];
__device__ float g_bond1[1000 * DIM];
__device__ float g_bond2[1000 * DIM];
__device__ int   g_ekey[N_EDGESC];
__device__ float g_sum[1024];
__device__ float g_sq[1024];
__device__ float g_scale[512];
__device__ float g_shift[512];

__device__ __forceinline__ void red_v4(float* addr, float a, float b, float c, float d) {
    asm volatile("red.global.add.v4.f32 [%0], {%1,%2,%3,%4};"
                 :: "l"(addr), "f"(a), "f"(b), "f"(c), "f"(d) : "memory");
}
__device__ __forceinline__ void cp_async16(void* smem, const void* gmem) {
    unsigned s = (unsigned)__cvta_generic_to_shared(smem);
    asm volatile("cp.async.cg.shared.global [%0], [%1], 16;" :: "r"(s), "l"(gmem));
}
__device__ __forceinline__ void cp_commit() { asm volatile("cp.async.commit_group;"); }
__device__ __forceinline__ void cp_wait0()  { asm volatile("cp.async.wait_group 0;"); }

// ---------------- zero helpers ----------------
__global__ void zero_stats() {
    int t = blockIdx.x * blockDim.x + threadIdx.x;
    if (t < 1024) { g_sum[t] = 0.f; g_sq[t] = 0.f; }
}
__global__ void zero_out(float* __restrict__ out) {
    int i = blockIdx.x * blockDim.x + threadIdx.x;
    if (i < N_GRAPHSC * DIM / 4) ((float4*)out)[i] = make_float4(0.f, 0.f, 0.f, 0.f);
}

// ---------------- bond combine: g_bond[k] = sum_c bemb[c, digit_c(k)] ----------------
__global__ void bond_combine(const float* __restrict__ be, float* __restrict__ dst) {
    int b = blockIdx.x;
    int a0 = b / 100, a1 = (b / 10) % 10, a2 = b % 10;
    int f = threadIdx.x;
    dst[(size_t)b * DIM + f] = be[(size_t)(0 * 10 + a0) * DIM + f]
                             + be[(size_t)(1 * 10 + a1) * DIM + f]
                             + be[(size_t)(2 * 10 + a2) * DIM + f];
}

__global__ void make_ekeys(const int* __restrict__ ea) {
    int e = blockIdx.x * blockDim.x + threadIdx.x;
    if (e >= N_EDGESC) return;
    g_ekey[e] = ea[(size_t)e * 3 + 0] * 100 + ea[(size_t)e * 3 + 1] * 10 + ea[(size_t)e * 3 + 2];
}

// ---------------- atom encoder (writes h and z) ----------------
__global__ void atom_encode(const int* __restrict__ x, const float* __restrict__ emb) {
    int n = blockIdx.x;
    __shared__ int xi[9];
    if (threadIdx.x < 9) xi[threadIdx.x] = x[n * 9 + threadIdx.x];
    __syncthreads();
    int f = threadIdx.x;
    float s = 0.f;
#pragma unroll
    for (int c = 0; c < 9; c++) s += emb[((size_t)(c * 100 + xi[c])) * DIM + f];
    g_h[(size_t)n * DIM + f] = s;
    g_z[(size_t)n * DIM + f] = s;
}

// ---------------- edge message passing ----------------
__global__ void edge_mp(const int* __restrict__ ei, const float* __restrict__ bond) {
    int e = (int)(((size_t)blockIdx.x * blockDim.x + threadIdx.x) >> 5);
    if (e >= N_EDGESC) return;
    int lane = threadIdx.x & 31;
    int src = __ldg(ei + e);
    int dst = __ldg(ei + N_EDGESC + e);
    int key = __ldg(g_ekey + e);
    const float* hs = g_h + (size_t)src * DIM;
    const float* bs = bond + (size_t)key * DIM;
    float*       zd = g_z + (size_t)dst * DIM;
#pragma unroll
    for (int i = 0; i < 2; i++) {
        int f = (lane + i * 32) * 4;
        float4 h4 = *(const float4*)(hs + f);
        float4 b4 = *(const float4*)(bs + f);
        red_v4(zd + f, fmaxf(h4.x + b4.x, 0.f), fmaxf(h4.y + b4.y, 0.f),
                       fmaxf(h4.z + b4.z, 0.f), fmaxf(h4.w + b4.w, 0.f));
    }
}

// ---------------- BN finalize + apply ----------------
__global__ void finstats(const float* __restrict__ gamma, const float* __restrict__ beta,
                         int Dh, int off) {
    int c = blockIdx.x * 256 + threadIdx.x;
    if (c >= Dh) return;
    float inv_n = 1.0f / (float)N_NODESC;
    float mu = g_sum[off + c] * inv_n;
    float var = g_sq[off + c] * inv_n - mu * mu;
    float rs = rsqrtf(var + EPSC);
    float sc = rs * gamma[c];
    g_scale[c] = sc;
    g_shift[c] = beta[c] - mu * sc;
}

template <int DH>
__global__ void bn_apply(float* __restrict__ Y, size_t n4) {
    size_t i = (size_t)blockIdx.x * blockDim.x + threadIdx.x;
    if (i >= n4) return;
    int c = (int)((i * 4) & (DH - 1));
    float4 v = ((const float4*)Y)[i];
    v.x = fmaxf(v.x * g_scale[c + 0] + g_shift[c + 0], 0.f);
    v.y = fmaxf(v.y * g_scale[c + 1] + g_shift[c + 1], 0.f);
    v.z = fmaxf(v.z * g_scale[c + 2] + g_shift[c + 2], 0.f);
    v.w = fmaxf(v.w * g_scale[c + 3] + g_shift[c + 3], 0.f);
    ((float4*)Y)[i] = v;
}

// ---------------- SGEMM 128x128x8, double-buffered ----------------
// RELU: relu output. STATS>=0: accumulate col sum/sumsq at offset STATS.
// STOREC: write C. C2: also write C2. POOL: scatter rows into pool_out by batch.
template <bool RELU, int STATS, bool STOREC, bool DUAL, bool POOL>
__global__ __launch_bounds__(256) void gemm128(
    const float* __restrict__ A, const float* __restrict__ B,
    const float* __restrict__ bias, float* __restrict__ C, float* __restrict__ C2,
    const int* __restrict__ batch, float* __restrict__ pool_out,
    int M, int K, int Nc) {
    const int BM = 128, BN = 128, BK = 8;
    __shared__ float As[2][BK][BM];
    __shared__ float Bs[2][BK][BN];
    __shared__ int sbatch[BM];

    int tid = threadIdx.x;
    int bm = blockIdx.y * BM;
    int bn = blockIdx.x * BN;

    int arow = tid >> 1;
    int akq  = (tid & 1) * 4;
    int brow = tid >> 5;
    int bcol = (tid & 31) * 4;
    int ty = tid >> 4;
    int tx = tid & 15;

    bool arow_ok = (bm + arow) < M;
    const float* aptr = A + (size_t)(bm + arow) * K + akq;
    const float* bptr = B + (size_t)brow * Nc + bn + bcol;

    if (POOL && tid < BM) sbatch[tid] = (bm + tid < M) ? batch[bm + tid] : (N_GRAPHSC - 1);

    float acc[8][8];
#pragma unroll
    for (int i = 0; i < 8; i++)
#pragma unroll
        for (int j = 0; j < 8; j++) acc[i][j] = 0.f;

    // prologue: buffer 0
    {
        float4 a4 = make_float4(0.f, 0.f, 0.f, 0.f);
        if (arow_ok) a4 = *(const float4*)(aptr);
        As[0][akq + 0][arow] = a4.x;
        As[0][akq + 1][arow] = a4.y;
        As[0][akq + 2][arow] = a4.z;
        As[0][akq + 3][arow] = a4.w;
        cp_async16(&Bs[0][brow][bcol], bptr);
        cp_commit();
        cp_wait0();
        __syncthreads();
    }

    int nIter = K / BK;
    for (int it = 0; it < nIter; it++) {
        int cur = it & 1, nxt = cur ^ 1;
        float4 a4;
        bool more = (it + 1 < nIter);
        if (more) {
            a4 = make_float4(0.f, 0.f, 0.f, 0.f);
            if (arow_ok) a4 = *(const float4*)(aptr + (size_t)(it + 1) * BK);
            cp_async16(&Bs[nxt][brow][bcol], bptr + (size_t)(it + 1) * BK * Nc);
            cp_commit();
        }
#pragma unroll
        for (int k = 0; k < BK; k++) {
            float a[8], b[8];
            *(float4*)&a[0] = *(const float4*)&As[cur][k][ty * 4];
            *(float4*)&a[4] = *(const float4*)&As[cur][k][64 + ty * 4];
            *(float4*)&b[0] = *(const float4*)&Bs[cur][k][tx * 4];
            *(float4*)&b[4] = *(const float4*)&Bs[cur][k][64 + tx * 4];
#pragma unroll
            for (int i = 0; i < 8; i++)
#pragma unroll
                for (int j = 0; j < 8; j++) acc[i][j] = fmaf(a[i], b[j], acc[i][j]);
        }
        if (more) {
            As[nxt][akq + 0][arow] = a4.x;
            As[nxt][akq + 1][arow] = a4.y;
            As[nxt][akq + 2][arow] = a4.z;
            As[nxt][akq + 3][arow] = a4.w;
            cp_wait0();
        }
        __syncthreads();
    }

    // epilogue
    float4 b_lo = *(const float4*)(bias + bn + tx * 4);
    float4 b_hi = *(const float4*)(bias + bn + 64 + tx * 4);
    float bb[8] = {b_lo.x, b_lo.y, b_lo.z, b_lo.w, b_hi.x, b_hi.y, b_hi.z, b_hi.w};

    float s[8], q[8];
    if (STATS >= 0) {
#pragma unroll
        for (int j = 0; j < 8; j++) { s[j] = 0.f; q[j] = 0.f; }
    }

    // pool run-merge state
    float pl[4], ph[4];
    int curb = -1;
    if (POOL) {
#pragma unroll
        for (int j = 0; j < 4; j++) { pl[j] = 0.f; ph[j] = 0.f; }
    }

#pragma unroll
    for (int i = 0; i < 8; i++) {
        int rloc = (i < 4) ? (ty * 4 + i) : (64 + ty * 4 + i - 4);
        int r = bm + rloc;
        if (r >= M) continue;
        float v[8];
#pragma unroll
        for (int j = 0; j < 8; j++) {
            v[j] = acc[i][j] + bb[j];
            if (RELU) v[j] = fmaxf(v[j], 0.f);
            if (STATS >= 0) { s[j] += v[j]; q[j] += v[j] * v[j]; }
        }
        if (STOREC) {
            float* crow = C + (size_t)r * Nc + bn;
            *(float4*)(crow + tx * 4)      = make_float4(v[0], v[1], v[2], v[3]);
            *(float4*)(crow + 64 + tx * 4) = make_float4(v[4], v[5], v[6], v[7]);
            if (DUAL) {
                float* c2row = C2 + (size_t)r * Nc + bn;
                *(float4*)(c2row + tx * 4)      = make_float4(v[0], v[1], v[2], v[3]);
                *(float4*)(c2row + 64 + tx * 4) = make_float4(v[4], v[5], v[6], v[7]);
            }
        }
        if (POOL) {
            int bg = sbatch[rloc];
            if (bg != curb) {
                if (curb >= 0) {
                    float* o = pool_out + (size_t)curb * DIM + bn;
                    red_v4(o + tx * 4, pl[0], pl[1], pl[2], pl[3]);
                    red_v4(o + 64 + tx * 4, ph[0], ph[1], ph[2], ph[3]);
#pragma unroll
                    for (int j = 0; j < 4; j++) { pl[j] = 0.f; ph[j] = 0.f; }
                }
                curb = bg;
            }
#pragma unroll
            for (int j = 0; j < 4; j++) { pl[j] += v[j]; ph[j] += v[4 + j]; }
        }
    }
    if (POOL && curb >= 0) {
        float* o = pool_out + (size_t)curb * DIM + bn;
        red_v4(o + tx * 4, pl[0], pl[1], pl[2], pl[3]);
        red_v4(o + 64 + tx * 4, ph[0], ph[1], ph[2], ph[3]);
    }
    if (STATS >= 0) {
#pragma unroll
        for (int j = 0; j < 8; j++) {
            int c = STATS + bn + ((j < 4) ? (tx * 4 + j) : (64 + tx * 4 + (j - 4)));
            atomicAdd(&g_sum[c], s[j]);
            atomicAdd(&g_sq[c], q[j]);
        }
    }
}

// ---------------- launch ----------------
extern "C" void kernel_launch(void* const* d_in, const int* in_sizes, int n_in,
                              void* d_out, int out_size) {
    const int* x      = (const int*)d_in[0];
    const int* ei     = (const int*)d_in[1];
    const int* ea     = (const int*)d_in[2];
    const int* batch  = (const int*)d_in[3];
    const float* atom = (const float*)d_in[4];
    const float* be1  = (const float*)d_in[5];
    const float* be2  = (const float*)d_in[6];
    const float* c1_w1 = (const float*)d_in[7];
    const float* c1_b1 = (const float*)d_in[8];
    const float* c1_g  = (const float*)d_in[9];
    const float* c1_be = (const float*)d_in[10];
    const float* c1_w2 = (const float*)d_in[11];
    const float* c1_b2 = (const float*)d_in[12];
    const float* c2_w1 = (const float*)d_in[13];
    const float* c2_b1 = (const float*)d_in[14];
    const float* c2_g  = (const float*)d_in[15];
    const float* c2_be = (const float*)d_in[16];
    const float* c2_w2 = (const float*)d_in[17];
    const float* c2_b2 = (const float*)d_in[18];
    float* out = (float*)d_out;

    float *hz, *zz, *yz, *b1z, *b2z;
    cudaGetSymbolAddress((void**)&hz, g_h);
    cudaGetSymbolAddress((void**)&zz, g_z);
    cudaGetSymbolAddress((void**)&yz, g_y);
    cudaGetSymbolAddress((void**)&b1z, g_bond1);
    cudaGetSymbolAddress((void**)&b2z, g_bond2);

    const int M = N_NODESC;
    const int edge_blocks = (N_EDGESC * 32 + 255) / 256;
    const int mtiles = (M + 127) / 128;
    dim3 gA(512 / 128, mtiles);
    dim3 gB(256 / 128, mtiles);
    size_t y1_4 = (size_t)M * 512 / 4, y2_4 = (size_t)M * 256 / 4;

    // setup
    zero_out<<<(N_GRAPHSC * DIM / 4 + 255) / 256, 256>>>(out);
    zero_stats<<<4, 256>>>();
    bond_combine<<<1000, 256>>>(be1, b1z);
    bond_combine<<<1000, 256>>>(be2, b2z);
    make_ekeys<<<(N_EDGESC + 255) / 256, 256>>>(ea);
    atom_encode<<<N_NODESC, 256>>>(x, atom);

    // ---- conv1 ----
    edge_mp<<<edge_blocks, 256>>>(ei, b1z);
    gemm128<false, 0, true, false, false><<<gA, 256>>>(zz, c1_w1, c1_b1, yz, nullptr, nullptr, nullptr, M, 256, 512);
    finstats<<<2, 256>>>(c1_g, c1_be, 512, 0);
    bn_apply<512><<<(int)((y1_4 + 255) / 256), 256>>>(yz, y1_4);
    gemm128<true, -1, true, true, false><<<gB, 256>>>(yz, c1_w2, c1_b2, hz, zz, nullptr, nullptr, M, 512, 256);

    // ---- conv2 ----
    edge_mp<<<edge_blocks, 256>>>(ei, b2z);
    gemm128<false, 512, true, false, false><<<gB, 256>>>(zz, c2_w1, c2_b1, yz, nullptr, nullptr, nullptr, M, 256, 256);
    finstats<<<1, 256>>>(c2_g, c2_be, 256, 512);
    bn_apply<256><<<(int)((y2_4 + 255) / 256), 256>>>(yz, y2_4);
    gemm128<true, -1, false, false, true><<<gB, 256>>>(yz, c2_w2, c2_b2, nullptr, nullptr, batch, out, M, 256, 256);
}

// round 5
// speedup vs baseline: 2.0374x; 1.2306x over previous
#include <cuda_runtime.h>
#include <cuda_bf16.h>
#include <cstddef>

#define N_NODESC 100000
#define N_EDGESC 3200000
#define N_GRAPHSC 2048
#define DIM 256
#define EPSC 1e-5f

// ---------------- scratch ----------------
__device__ float g_h[(size_t)N_NODESC * DIM];
__device__ float g_z[(size_t)N_NODESC * DIM];
__device__ float g_y[(size_t)N_NODESC * 2 * DIM];
__device__ float g_bond[2000 * DIM];            // [0:1000) conv1, [1000:2000) conv2
__device__ int   g_deg[N_NODESC + 1];
__device__ int   g_off[N_NODESC + 1];
__device__ int   g_pos[N_NODESC];
__device__ int2  g_csr[N_EDGESC];               // (src, bond_key)
__device__ float g_sum[1024];
__device__ float g_sq[1024];
__device__ float g_scale[512];
__device__ float g_shift[512];

__device__ __forceinline__ void red_v4(float* addr, float a, float b, float c, float d) {
    asm volatile("red.global.add.v4.f32 [%0], {%1,%2,%3,%4};"
                 :: "l"(addr), "f"(a), "f"(b), "f"(c), "f"(d) : "memory");
}
__device__ __forceinline__ void cp_async16(void* smem, const void* gmem) {
    unsigned s = (unsigned)__cvta_generic_to_shared(smem);
    asm volatile("cp.async.cg.shared.global [%0], [%1], 16;" :: "r"(s), "l"(gmem));
}
__device__ __forceinline__ void cp_commit() { asm volatile("cp.async.commit_group;"); }
__device__ __forceinline__ void cp_wait0()  { asm volatile("cp.async.wait_group 0;"); }

// ---------------- setup: zero deg/stats/out ----------------
__global__ void setup_zero(float* __restrict__ out) {
    int i = blockIdx.x * 256 + threadIdx.x;
    if (i <= N_NODESC) g_deg[i] = 0;
    if (i < 1024) { g_sum[i] = 0.f; g_sq[i] = 0.f; }
    if (i < N_GRAPHSC * DIM / 4) ((float4*)out)[i] = make_float4(0.f, 0.f, 0.f, 0.f);
}

// ---------------- CSR build ----------------
__global__ void hist(const int* __restrict__ ei) {
    int e = blockIdx.x * blockDim.x + threadIdx.x;
    if (e < N_EDGESC) atomicAdd(&g_deg[__ldg(ei + N_EDGESC + e)], 1);
}

__global__ void scan_offsets() {
    const int CH = 98;  // 1024*98 = 100352 >= 100001
    __shared__ int ssum[1024];
    int t = threadIdx.x;
    int base = t * CH;
    int local = 0;
    for (int i = 0; i < CH; i++) {
        int idx = base + i;
        if (idx <= N_NODESC) local += g_deg[idx];
    }
    ssum[t] = local;
    __syncthreads();
    for (int off = 1; off < 1024; off <<= 1) {
        int v = (t >= off) ? ssum[t - off] : 0;
        __syncthreads();
        if (t >= off) ssum[t] += v;
        __syncthreads();
    }
    int run = (t == 0) ? 0 : ssum[t - 1];
    for (int i = 0; i < CH; i++) {
        int idx = base + i;
        if (idx <= N_NODESC) {
            int d = g_deg[idx];
            g_off[idx] = run;
            if (idx < N_NODESC) g_pos[idx] = run;
            run += d;
        }
    }
}

__global__ void fill_csr(const int* __restrict__ ei, const int* __restrict__ ea) {
    int e = blockIdx.x * blockDim.x + threadIdx.x;
    if (e >= N_EDGESC) return;
    int src = __ldg(ei + e);
    int dst = __ldg(ei + N_EDGESC + e);
    int key = __ldg(ea + (size_t)e * 3 + 0) * 100
            + __ldg(ea + (size_t)e * 3 + 1) * 10
            + __ldg(ea + (size_t)e * 3 + 2);
    int slot = atomicAdd(&g_pos[dst], 1);
    g_csr[slot] = make_int2(src, key);
}

// ---------------- bond combine (both tables) ----------------
__global__ void bond_combine(const float* __restrict__ be1, const float* __restrict__ be2) {
    int b = blockIdx.x;                 // 0..1999
    const float* be = (b < 1000) ? be1 : be2;
    int k = (b < 1000) ? b : b - 1000;
    int a0 = k / 100, a1 = (k / 10) % 10, a2 = k % 10;
    int f = threadIdx.x;
    g_bond[(size_t)b * DIM + f] = be[(size_t)(0 * 10 + a0) * DIM + f]
                                + be[(size_t)(1 * 10 + a1) * DIM + f]
                                + be[(size_t)(2 * 10 + a2) * DIM + f];
}

// ---------------- atom encoder ----------------
__global__ void atom_encode(const int* __restrict__ x, const float* __restrict__ emb) {
    int n = blockIdx.x;
    __shared__ int xi[9];
    if (threadIdx.x < 9) xi[threadIdx.x] = x[n * 9 + threadIdx.x];
    __syncthreads();
    int f = threadIdx.x;
    float s = 0.f;
#pragma unroll
    for (int c = 0; c < 9; c++) s += emb[((size_t)(c * 100 + xi[c])) * DIM + f];
    g_h[(size_t)n * DIM + f] = s;
}

// ---------------- gather: z[n] = h[n] + sum_{e->n} relu(h[src]+bond[key]) ----------------
__global__ void gather_mp(const float* __restrict__ bond) {
    int n = (int)(((size_t)blockIdx.x * blockDim.x + threadIdx.x) >> 5);
    if (n >= N_NODESC) return;
    int lane = threadIdx.x & 31;
    int f1 = lane * 4, f2 = 128 + lane * 4;
    const float* hd = g_h + (size_t)n * DIM;
    float4 a0 = *(const float4*)(hd + f1);
    float4 a1 = *(const float4*)(hd + f2);
    int p = g_off[n], pe = g_off[n + 1];
    for (; p < pe; p++) {
        int2 sk = __ldg(&g_csr[p]);
        const float* hs = g_h + (size_t)sk.x * DIM;
        const float* bs = bond + (size_t)sk.y * DIM;
        float4 h1 = *(const float4*)(hs + f1);
        float4 b1 = *(const float4*)(bs + f1);
        float4 h2 = *(const float4*)(hs + f2);
        float4 b2 = *(const float4*)(bs + f2);
        a0.x += fmaxf(h1.x + b1.x, 0.f);
        a0.y += fmaxf(h1.y + b1.y, 0.f);
        a0.z += fmaxf(h1.z + b1.z, 0.f);
        a0.w += fmaxf(h1.w + b1.w, 0.f);
        a1.x += fmaxf(h2.x + b2.x, 0.f);
        a1.y += fmaxf(h2.y + b2.y, 0.f);
        a1.z += fmaxf(h2.z + b2.z, 0.f);
        a1.w += fmaxf(h2.w + b2.w, 0.f);
    }
    float* zd = g_z + (size_t)n * DIM;
    *(float4*)(zd + f1) = a0;
    *(float4*)(zd + f2) = a1;
}

// ---------------- BN finalize ----------------
__global__ void finstats(const float* __restrict__ gamma, const float* __restrict__ beta,
                         int Dh, int off) {
    int c = blockIdx.x * 256 + threadIdx.x;
    if (c >= Dh) return;
    float inv_n = 1.0f / (float)N_NODESC;
    float mu = g_sum[off + c] * inv_n;
    float var = g_sq[off + c] * inv_n - mu * mu;
    float rs = rsqrtf(var + EPSC);
    float sc = rs * gamma[c];
    g_scale[c] = sc;
    g_shift[c] = beta[c] - mu * sc;
}

// ---------------- SGEMM 128x128x8, double-buffered B via cp.async ----------------
// TRANSFORM: A elem -> relu(a*scale[k]+shift[k]). RELU: relu output.
// STATS>=0: col sum/sumsq at offset. STOREC: write C. POOL: row-scatter into pool_out.
template <bool TRANSFORM, bool RELU, int STATS, bool STOREC, bool POOL>
__global__ __launch_bounds__(256) void gemm128(
    const float* __restrict__ A, const float* __restrict__ B,
    const float* __restrict__ bias, float* __restrict__ C,
    const int* __restrict__ batch, float* __restrict__ pool_out,
    int M, int K, int Nc) {
    const int BM = 128, BN = 128, BK = 8;
    __shared__ float As[2][BK][BM];
    __shared__ float Bs[2][BK][BN];
    __shared__ int sbatch[BM];

    int tid = threadIdx.x;
    int bm = blockIdx.y * BM;
    int bn = blockIdx.x * BN;

    int arow = tid >> 1;
    int akq  = (tid & 1) * 4;
    int brow = tid >> 5;
    int bcol = (tid & 31) * 4;
    int ty = tid >> 4;
    int tx = tid & 15;

    bool arow_ok = (bm + arow) < M;
    const float* aptr = A + (size_t)(bm + arow) * K + akq;
    const float* bptr = B + (size_t)brow * Nc + bn + bcol;

    if (POOL && tid < BM) sbatch[tid] = (bm + tid < M) ? batch[bm + tid] : 0;

    float acc[8][8];
#pragma unroll
    for (int i = 0; i < 8; i++)
#pragma unroll
        for (int j = 0; j < 8; j++) acc[i][j] = 0.f;

    // prologue: buffer 0
    {
        float4 a4 = make_float4(0.f, 0.f, 0.f, 0.f);
        if (arow_ok) a4 = *(const float4*)(aptr);
        if (TRANSFORM) {
            a4.x = fmaxf(a4.x * g_scale[akq + 0] + g_shift[akq + 0], 0.f);
            a4.y = fmaxf(a4.y * g_scale[akq + 1] + g_shift[akq + 1], 0.f);
            a4.z = fmaxf(a4.z * g_scale[akq + 2] + g_shift[akq + 2], 0.f);
            a4.w = fmaxf(a4.w * g_scale[akq + 3] + g_shift[akq + 3], 0.f);
        }
        As[0][akq + 0][arow] = a4.x;
        As[0][akq + 1][arow] = a4.y;
        As[0][akq + 2][arow] = a4.z;
        As[0][akq + 3][arow] = a4.w;
        cp_async16(&Bs[0][brow][bcol], bptr);
        cp_commit();
        cp_wait0();
        __syncthreads();
    }

    int nIter = K / BK;
    for (int it = 0; it < nIter; it++) {
        int cur = it & 1, nxt = cur ^ 1;
        float4 a4;
        bool more = (it + 1 < nIter);
        if (more) {
            a4 = make_float4(0.f, 0.f, 0.f, 0.f);
            if (arow_ok) a4 = *(const float4*)(aptr + (size_t)(it + 1) * BK);
            if (TRANSFORM) {
                int kb = (it + 1) * BK + akq;
                a4.x = fmaxf(a4.x * g_scale[kb + 0] + g_shift[kb + 0], 0.f);
                a4.y = fmaxf(a4.y * g_scale[kb + 1] + g_shift[kb + 1], 0.f);
                a4.z = fmaxf(a4.z * g_scale[kb + 2] + g_shift[kb + 2], 0.f);
                a4.w = fmaxf(a4.w * g_scale[kb + 3] + g_shift[kb + 3], 0.f);
            }
            cp_async16(&Bs[nxt][brow][bcol], bptr + (size_t)(it + 1) * BK * Nc);
            cp_commit();
        }
#pragma unroll
        for (int k = 0; k < BK; k++) {
            float a[8], b[8];
            *(float4*)&a[0] = *(const float4*)&As[cur][k][ty * 4];
            *(float4*)&a[4] = *(const float4*)&As[cur][k][64 + ty * 4];
            *(float4*)&b[0] = *(const float4*)&Bs[cur][k][tx * 4];
            *(float4*)&b[4] = *(const float4*)&Bs[cur][k][64 + tx * 4];
#pragma unroll
            for (int i = 0; i < 8; i++)
#pragma unroll
                for (int j = 0; j < 8; j++) acc[i][j] = fmaf(a[i], b[j], acc[i][j]);
        }
        if (more) {
            As[nxt][akq + 0][arow] = a4.x;
            As[nxt][akq + 1][arow] = a4.y;
            As[nxt][akq + 2][arow] = a4.z;
            As[nxt][akq + 3][arow] = a4.w;
            cp_wait0();
        }
        __syncthreads();
    }

    // epilogue
    float4 b_lo = *(const float4*)(bias + bn + tx * 4);
    float4 b_hi = *(const float4*)(bias + bn + 64 + tx * 4);
    float bb[8] = {b_lo.x, b_lo.y, b_lo.z, b_lo.w, b_hi.x, b_hi.y, b_hi.z, b_hi.w};

    float s[8], q[8];
    if (STATS >= 0) {
#pragma unroll
        for (int j = 0; j < 8; j++) { s[j] = 0.f; q[j] = 0.f; }
    }

    float pl[4], ph[4];
    int curb = -1;
    if (POOL) {
#pragma unroll
        for (int j = 0; j < 4; j++) { pl[j] = 0.f; ph[j] = 0.f; }
    }

#pragma unroll
    for (int i = 0; i < 8; i++) {
        int rloc = (i < 4) ? (ty * 4 + i) : (64 + ty * 4 + i - 4);
        int r = bm + rloc;
        if (r >= M) continue;
        float v[8];
#pragma unroll
        for (int j = 0; j < 8; j++) {
            v[j] = acc[i][j] + bb[j];
            if (RELU) v[j] = fmaxf(v[j], 0.f);
            if (STATS >= 0) { s[j] += v[j]; q[j] += v[j] * v[j]; }
        }
        if (STOREC) {
            float* crow = C + (size_t)r * Nc + bn;
            *(float4*)(crow + tx * 4)      = make_float4(v[0], v[1], v[2], v[3]);
            *(float4*)(crow + 64 + tx * 4) = make_float4(v[4], v[5], v[6], v[7]);
        }
        if (POOL) {
            int bg = sbatch[rloc];
            if (bg != curb) {
                if (curb >= 0) {
                    float* o = pool_out + (size_t)curb * DIM + bn;
                    red_v4(o + tx * 4, pl[0], pl[1], pl[2], pl[3]);
                    red_v4(o + 64 + tx * 4, ph[0], ph[1], ph[2], ph[3]);
#pragma unroll
                    for (int j = 0; j < 4; j++) { pl[j] = 0.f; ph[j] = 0.f; }
                }
                curb = bg;
            }
#pragma unroll
            for (int j = 0; j < 4; j++) { pl[j] += v[j]; ph[j] += v[4 + j]; }
        }
    }
    if (POOL && curb >= 0) {
        float* o = pool_out + (size_t)curb * DIM + bn;
        red_v4(o + tx * 4, pl[0], pl[1], pl[2], pl[3]);
        red_v4(o + 64 + tx * 4, ph[0], ph[1], ph[2], ph[3]);
    }
    if (STATS >= 0) {
#pragma unroll
        for (int j = 0; j < 8; j++) {
            int c = STATS + bn + ((j < 4) ? (tx * 4 + j) : (64 + tx * 4 + (j - 4)));
            atomicAdd(&g_sum[c], s[j]);
            atomicAdd(&g_sq[c], q[j]);
        }
    }
}

// ---------------- launch ----------------
extern "C" void kernel_launch(void* const* d_in, const int* in_sizes, int n_in,
                              void* d_out, int out_size) {
    const int* x      = (const int*)d_in[0];
    const int* ei     = (const int*)d_in[1];
    const int* ea     = (const int*)d_in[2];
    const int* batch  = (const int*)d_in[3];
    const float* atom = (const float*)d_in[4];
    const float* be1  = (const float*)d_in[5];
    const float* be2  = (const float*)d_in[6];
    const float* c1_w1 = (const float*)d_in[7];
    const float* c1_b1 = (const float*)d_in[8];
    const float* c1_g  = (const float*)d_in[9];
    const float* c1_be = (const float*)d_in[10];
    const float* c1_w2 = (const float*)d_in[11];
    const float* c1_b2 = (const float*)d_in[12];
    const float* c2_w1 = (const float*)d_in[13];
    const float* c2_b1 = (const float*)d_in[14];
    const float* c2_g  = (const float*)d_in[15];
    const float* c2_be = (const float*)d_in[16];
    const float* c2_w2 = (const float*)d_in[17];
    const float* c2_b2 = (const float*)d_in[18];
    float* out = (float*)d_out;

    float *hz, *zz, *yz, *bz;
    cudaGetSymbolAddress((void**)&hz, g_h);
    cudaGetSymbolAddress((void**)&zz, g_z);
    cudaGetSymbolAddress((void**)&yz, g_y);
    cudaGetSymbolAddress((void**)&bz, g_bond);

    const int M = N_NODESC;
    const int eb = (N_EDGESC + 255) / 256;
    const int gb = (N_NODESC * 32 + 255) / 256;   // warp per node
    const int mtiles = (M + 127) / 128;
    dim3 gA(512 / 128, mtiles);
    dim3 gB(256 / 128, mtiles);

    // setup + CSR build (topology shared by both convs)
    setup_zero<<<512, 256>>>(out);
    hist<<<eb, 256>>>(ei);
    scan_offsets<<<1, 1024>>>();
    fill_csr<<<eb, 256>>>(ei, ea);
    bond_combine<<<2000, 256>>>(be1, be2);
    atom_encode<<<N_NODESC, 256>>>(x, atom);

    // ---- conv1 ----
    gather_mp<<<gb, 256>>>(bz);
    gemm128<false, false, 0, true, false><<<gA, 256>>>(zz, c1_w1, c1_b1, yz, nullptr, nullptr, M, 256, 512);
    finstats<<<2, 256>>>(c1_g, c1_be, 512, 0);
    gemm128<true, true, -1, true, false><<<gB, 256>>>(yz, c1_w2, c1_b2, hz, nullptr, nullptr, M, 512, 256);

    // ---- conv2 ----
    gather_mp<<<gb, 256>>>(bz + (size_t)1000 * DIM);
    gemm128<false, false, 512, true, false><<<gB, 256>>>(zz, c2_w1, c2_b1, yz, nullptr, nullptr, M, 256, 256);
    finstats<<<1, 256>>>(c2_g, c2_be, 256, 512);
    gemm128<true, true, -1, false, true><<<gB, 256>>>(yz, c2_w2, c2_b2, nullptr, batch, out, M, 256, 256);
}

// round 6
// speedup vs baseline: 3.6603x; 1.7966x over previous
#include <cuda_runtime.h>
#include <cuda_bf16.h>
#include <cstddef>
#include <cstdint>

#define N_NODESC 100000
#define N_EDGESC 3200000
#define N_GRAPHSC 2048
#define DIM 256
#define EPSC 1e-5f

// ---------------- scratch ----------------
__device__ float g_h[(size_t)N_NODESC * DIM];
__device__ float g_z[(size_t)N_NODESC * DIM];
__device__ float g_y[(size_t)N_NODESC * 2 * DIM];
__device__ float g_bond[2000 * DIM];
__device__ int   g_deg[N_NODESC + 1];
__device__ int   g_off[N_NODESC + 1];
__device__ int   g_pos[N_NODESC];
__device__ int2  g_csr[N_EDGESC];
__device__ float g_sum[1024];
__device__ float g_sq[1024];
__device__ float g_scale[512];
__device__ float g_shift[512];

__device__ __forceinline__ void red_v4(float* addr, float a, float b, float c, float d) {
    asm volatile("red.global.add.v4.f32 [%0], {%1,%2,%3,%4};"
                 :: "l"(addr), "f"(a), "f"(b), "f"(c), "f"(d) : "memory");
}
__device__ __forceinline__ float to_tf32(float x) {
    uint32_t r;
    asm("cvt.rna.tf32.f32 %0, %1;" : "=r"(r) : "f"(x));
    return __uint_as_float(r);
}
__device__ __forceinline__ void mma_tf32(float c[4], const uint32_t a[4], const uint32_t b[2]) {
    asm volatile(
        "mma.sync.aligned.m16n8k8.row.col.f32.tf32.tf32.f32 "
        "{%0,%1,%2,%3}, {%4,%5,%6,%7}, {%8,%9}, {%0,%1,%2,%3};"
        : "+f"(c[0]), "+f"(c[1]), "+f"(c[2]), "+f"(c[3])
        : "r"(a[0]), "r"(a[1]), "r"(a[2]), "r"(a[3]), "r"(b[0]), "r"(b[1]));
}

// ---------------- setup ----------------
__global__ void setup_zero(float* __restrict__ out) {
    int i = blockIdx.x * 256 + threadIdx.x;
    if (i <= N_NODESC) g_deg[i] = 0;
    if (i < 1024) { g_sum[i] = 0.f; g_sq[i] = 0.f; }
    if (i < N_GRAPHSC * DIM / 4) ((float4*)out)[i] = make_float4(0.f, 0.f, 0.f, 0.f);
}

// ---------------- CSR build ----------------
__global__ void hist(const int* __restrict__ ei) {
    int e = blockIdx.x * blockDim.x + threadIdx.x;
    if (e < N_EDGESC) atomicAdd(&g_deg[__ldg(ei + N_EDGESC + e)], 1);
}

__global__ void scan_offsets() {
    const int CH = 98;
    __shared__ int ssum[1024];
    int t = threadIdx.x;
    int base = t * CH;
    int local = 0;
    for (int i = 0; i < CH; i++) {
        int idx = base + i;
        if (idx <= N_NODESC) local += g_deg[idx];
    }
    ssum[t] = local;
    __syncthreads();
    for (int off = 1; off < 1024; off <<= 1) {
        int v = (t >= off) ? ssum[t - off] : 0;
        __syncthreads();
        if (t >= off) ssum[t] += v;
        __syncthreads();
    }
    int run = (t == 0) ? 0 : ssum[t - 1];
    for (int i = 0; i < CH; i++) {
        int idx = base + i;
        if (idx <= N_NODESC) {
            int d = g_deg[idx];
            g_off[idx] = run;
            if (idx < N_NODESC) g_pos[idx] = run;
            run += d;
        }
    }
}

__global__ void fill_csr(const int* __restrict__ ei, const int* __restrict__ ea) {
    int e = blockIdx.x * blockDim.x + threadIdx.x;
    if (e >= N_EDGESC) return;
    int src = __ldg(ei + e);
    int dst = __ldg(ei + N_EDGESC + e);
    int key = __ldg(ea + (size_t)e * 3 + 0) * 100
            + __ldg(ea + (size_t)e * 3 + 1) * 10
            + __ldg(ea + (size_t)e * 3 + 2);
    int slot = atomicAdd(&g_pos[dst], 1);
    g_csr[slot] = make_int2(src, key);
}

// ---------------- bond combine ----------------
__global__ void bond_combine(const float* __restrict__ be1, const float* __restrict__ be2) {
    int b = blockIdx.x;
    const float* be = (b < 1000) ? be1 : be2;
    int k = (b < 1000) ? b : b - 1000;
    int a0 = k / 100, a1 = (k / 10) % 10, a2 = k % 10;
    int f = threadIdx.x;
    g_bond[(size_t)b * DIM + f] = be[(size_t)(0 * 10 + a0) * DIM + f]
                                + be[(size_t)(1 * 10 + a1) * DIM + f]
                                + be[(size_t)(2 * 10 + a2) * DIM + f];
}

// ---------------- atom encoder ----------------
__global__ void atom_encode(const int* __restrict__ x, const float* __restrict__ emb) {
    int n = blockIdx.x;
    __shared__ int xi[9];
    if (threadIdx.x < 9) xi[threadIdx.x] = x[n * 9 + threadIdx.x];
    __syncthreads();
    int f = threadIdx.x;
    float s = 0.f;
#pragma unroll
    for (int c = 0; c < 9; c++) s += emb[((size_t)(c * 100 + xi[c])) * DIM + f];
    g_h[(size_t)n * DIM + f] = s;
}

// ---------------- gather ----------------
__global__ void gather_mp(const float* __restrict__ bond) {
    int n = (int)(((size_t)blockIdx.x * blockDim.x + threadIdx.x) >> 5);
    if (n >= N_NODESC) return;
    int lane = threadIdx.x & 31;
    int f1 = lane * 4, f2 = 128 + lane * 4;
    const float* hd = g_h + (size_t)n * DIM;
    float4 a0 = *(const float4*)(hd + f1);
    float4 a1 = *(const float4*)(hd + f2);
    int p = g_off[n], pe = g_off[n + 1];
    for (; p < pe; p++) {
        int2 sk = __ldg(&g_csr[p]);
        const float* hs = g_h + (size_t)sk.x * DIM;
        const float* bs = bond + (size_t)sk.y * DIM;
        float4 h1 = *(const float4*)(hs + f1);
        float4 b1 = *(const float4*)(bs + f1);
        float4 h2 = *(const float4*)(hs + f2);
        float4 b2 = *(const float4*)(bs + f2);
        a0.x += fmaxf(h1.x + b1.x, 0.f);
        a0.y += fmaxf(h1.y + b1.y, 0.f);
        a0.z += fmaxf(h1.z + b1.z, 0.f);
        a0.w += fmaxf(h1.w + b1.w, 0.f);
        a1.x += fmaxf(h2.x + b2.x, 0.f);
        a1.y += fmaxf(h2.y + b2.y, 0.f);
        a1.z += fmaxf(h2.z + b2.z, 0.f);
        a1.w += fmaxf(h2.w + b2.w, 0.f);
    }
    float* zd = g_z + (size_t)n * DIM;
    *(float4*)(zd + f1) = a0;
    *(float4*)(zd + f2) = a1;
}

// ---------------- BN finalize ----------------
__global__ void finstats(const float* __restrict__ gamma, const float* __restrict__ beta,
                         int Dh, int off) {
    int c = blockIdx.x * 256 + threadIdx.x;
    if (c >= Dh) return;
    float inv_n = 1.0f / (float)N_NODESC;
    float mu = g_sum[off + c] * inv_n;
    float var = g_sq[off + c] * inv_n - mu * mu;
    float rs = rsqrtf(var + EPSC);
    float sc = rs * gamma[c];
    g_scale[c] = sc;
    g_shift[c] = beta[c] - mu * sc;
}

// ---------------- tf32 tensor-core GEMM 128x128x16 ----------------
// 256 threads = 8 warps, warp tile 64x32 via m16n8k8.
// TRANSFORM: A elem -> relu(a*scale[k]+shift[k]) before tf32 round.
// RELU: relu output. STATS>=0: fused col sum/sumsq at that offset.
template <bool TRANSFORM, bool RELU, int STATS>
__global__ __launch_bounds__(256) void gemm_tc(
    const float* __restrict__ A, const float* __restrict__ B,
    const float* __restrict__ bias, float* __restrict__ C,
    int M, int K, int Nc) {
    const int BM = 128, BN = 128, BK = 16;
    const int BKP = BK + 4;    // A row pad
    const int BNP = BN + 4;    // B row pad
    __shared__ float As[2][BM][BKP];
    __shared__ float Bs[2][BK][BNP];

    int tid = threadIdx.x;
    int lane = tid & 31;
    int wid = tid >> 5;
    int wm = wid & 1;          // 0..1 -> 64-row halves
    int wn = wid >> 1;         // 0..3 -> 32-col quarters
    int bm = blockIdx.y * BM;
    int bn = blockIdx.x * BN;

    // loader indexing: two float4 per thread for each of A and B
    int idx0 = tid, idx1 = tid + 256;
    int ar0 = idx0 >> 2, ak0 = (idx0 & 3) * 4;
    int ar1 = idx1 >> 2, ak1 = (idx1 & 3) * 4;
    int br0 = idx0 >> 5, bq0 = (idx0 & 31) * 4;
    int br1 = idx1 >> 5, bq1 = (idx1 & 31) * 4;
    bool aok0 = (bm + ar0) < M;
    bool aok1 = (bm + ar1) < M;

    float c[4][4][4];
#pragma unroll
    for (int mt = 0; mt < 4; mt++)
#pragma unroll
        for (int nt = 0; nt < 4; nt++)
#pragma unroll
            for (int r = 0; r < 4; r++) c[mt][nt][r] = 0.f;

    float4 a4s[2], b4s[2];

    auto ldg_tile = [&](int k0) {
        a4s[0] = aok0 ? *(const float4*)(A + (size_t)(bm + ar0) * K + k0 + ak0)
                      : make_float4(0.f, 0.f, 0.f, 0.f);
        a4s[1] = aok1 ? *(const float4*)(A + (size_t)(bm + ar1) * K + k0 + ak1)
                      : make_float4(0.f, 0.f, 0.f, 0.f);
        if (TRANSFORM) {
#pragma unroll
            for (int t = 0; t < 2; t++) {
                int kb = k0 + ((t == 0) ? ak0 : ak1);
                float4& v = a4s[t];
                v.x = fmaxf(v.x * g_scale[kb + 0] + g_shift[kb + 0], 0.f);
                v.y = fmaxf(v.y * g_scale[kb + 1] + g_shift[kb + 1], 0.f);
                v.z = fmaxf(v.z * g_scale[kb + 2] + g_shift[kb + 2], 0.f);
                v.w = fmaxf(v.w * g_scale[kb + 3] + g_shift[kb + 3], 0.f);
            }
        }
        b4s[0] = *(const float4*)(B + (size_t)(k0 + br0) * Nc + bn + bq0);
        b4s[1] = *(const float4*)(B + (size_t)(k0 + br1) * Nc + bn + bq1);
    };
    auto sts_tile = [&](int buf) {
        float* a0 = &As[buf][ar0][ak0];
        a0[0] = to_tf32(a4s[0].x); a0[1] = to_tf32(a4s[0].y);
        a0[2] = to_tf32(a4s[0].z); a0[3] = to_tf32(a4s[0].w);
        float* a1 = &As[buf][ar1][ak1];
        a1[0] = to_tf32(a4s[1].x); a1[1] = to_tf32(a4s[1].y);
        a1[2] = to_tf32(a4s[1].z); a1[3] = to_tf32(a4s[1].w);
        float* b0 = &Bs[buf][br0][bq0];
        b0[0] = to_tf32(b4s[0].x); b0[1] = to_tf32(b4s[0].y);
        b0[2] = to_tf32(b4s[0].z); b0[3] = to_tf32(b4s[0].w);
        float* b1 = &Bs[buf][br1][bq1];
        b1[0] = to_tf32(b4s[1].x); b1[1] = to_tf32(b4s[1].y);
        b1[2] = to_tf32(b4s[1].z); b1[3] = to_tf32(b4s[1].w);
    };

    // prologue
    ldg_tile(0);
    sts_tile(0);
    __syncthreads();

    int nIter = K / BK;
    int lq = lane >> 2;   // 0..7
    int lr = lane & 3;    // 0..3
    for (int it = 0; it < nIter; it++) {
        int cur = it & 1, nxt = cur ^ 1;
        bool more = (it + 1 < nIter);
        if (more) ldg_tile((it + 1) * BK);

#pragma unroll
        for (int ks = 0; ks < 2; ks++) {
            int k0 = ks * 8;
            uint32_t bf[4][2];
#pragma unroll
            for (int nt = 0; nt < 4; nt++) {
                int ncol = wn * 32 + nt * 8 + lq;
                bf[nt][0] = __float_as_uint(Bs[cur][k0 + lr][ncol]);
                bf[nt][1] = __float_as_uint(Bs[cur][k0 + 4 + lr][ncol]);
            }
#pragma unroll
            for (int mt = 0; mt < 4; mt++) {
                int mrow = wm * 64 + mt * 16 + lq;
                uint32_t af[4];
                af[0] = __float_as_uint(As[cur][mrow][k0 + lr]);
                af[1] = __float_as_uint(As[cur][mrow + 8][k0 + lr]);
                af[2] = __float_as_uint(As[cur][mrow][k0 + 4 + lr]);
                af[3] = __float_as_uint(As[cur][mrow + 8][k0 + 4 + lr]);
#pragma unroll
                for (int nt = 0; nt < 4; nt++) mma_tf32(c[mt][nt], af, bf[nt]);
            }
        }
        if (more) sts_tile(nxt);
        __syncthreads();
    }

    // ---------------- epilogue ----------------
    float2 bias2[4];
    int cbase[4];
#pragma unroll
    for (int nt = 0; nt < 4; nt++) {
        cbase[nt] = bn + wn * 32 + nt * 8 + lr * 2;
        bias2[nt] = *(const float2*)(bias + cbase[nt]);
    }

    float sx[4][2], qx[4][2];
    if (STATS >= 0) {
#pragma unroll
        for (int nt = 0; nt < 4; nt++) { sx[nt][0] = sx[nt][1] = 0.f; qx[nt][0] = qx[nt][1] = 0.f; }
    }

#pragma unroll
    for (int mt = 0; mt < 4; mt++) {
        int r0 = bm + wm * 64 + mt * 16 + lq;
        int r1 = r0 + 8;
        bool ok0 = r0 < M, ok1 = r1 < M;
#pragma unroll
        for (int nt = 0; nt < 4; nt++) {
            float v00 = c[mt][nt][0] + bias2[nt].x;
            float v01 = c[mt][nt][1] + bias2[nt].y;
            float v10 = c[mt][nt][2] + bias2[nt].x;
            float v11 = c[mt][nt][3] + bias2[nt].y;
            if (RELU) {
                v00 = fmaxf(v00, 0.f); v01 = fmaxf(v01, 0.f);
                v10 = fmaxf(v10, 0.f); v11 = fmaxf(v11, 0.f);
            }
            if (ok0) {
                *(float2*)(C + (size_t)r0 * Nc + cbase[nt]) = make_float2(v00, v01);
                if (STATS >= 0) {
                    sx[nt][0] += v00; sx[nt][1] += v01;
                    qx[nt][0] += v00 * v00; qx[nt][1] += v01 * v01;
                }
            }
            if (ok1) {
                *(float2*)(C + (size_t)r1 * Nc + cbase[nt]) = make_float2(v10, v11);
                if (STATS >= 0) {
                    sx[nt][0] += v10; sx[nt][1] += v11;
                    qx[nt][0] += v10 * v10; qx[nt][1] += v11 * v11;
                }
            }
        }
    }

    if (STATS >= 0) {
        // reduce across the 8 row-groups (lanes differing in lane>>2)
#pragma unroll
        for (int nt = 0; nt < 4; nt++) {
#pragma unroll
            for (int h = 0; h < 2; h++) {
#pragma unroll
                for (int off = 4; off < 32; off <<= 1) {
                    sx[nt][h] += __shfl_xor_sync(0xffffffffu, sx[nt][h], off);
                    qx[nt][h] += __shfl_xor_sync(0xffffffffu, qx[nt][h], off);
                }
            }
        }
        if (lane < 4) {
#pragma unroll
            for (int nt = 0; nt < 4; nt++) {
                atomicAdd(&g_sum[STATS + cbase[nt] + 0], sx[nt][0]);
                atomicAdd(&g_sum[STATS + cbase[nt] + 1], sx[nt][1]);
                atomicAdd(&g_sq[STATS + cbase[nt] + 0], qx[nt][0]);
                atomicAdd(&g_sq[STATS + cbase[nt] + 1], qx[nt][1]);
            }
        }
    }
}

// ---------------- global add pool ----------------
__global__ void pool_kernel(const int* __restrict__ batch, float* __restrict__ out) {
    int n = (int)(((size_t)blockIdx.x * blockDim.x + threadIdx.x) >> 5);
    if (n >= N_NODESC) return;
    int lane = threadIdx.x & 31;
    int gidx = __ldg(batch + n);
    const float* h = g_h + (size_t)n * DIM;
    float* o = out + (size_t)gidx * DIM;
#pragma unroll
    for (int i = 0; i < 2; i++) {
        int f = (lane + i * 32) * 4;
        float4 v = *(const float4*)(h + f);
        red_v4(o + f, v.x, v.y, v.z, v.w);
    }
}

// ---------------- launch ----------------
extern "C" void kernel_launch(void* const* d_in, const int* in_sizes, int n_in,
                              void* d_out, int out_size) {
    const int* x      = (const int*)d_in[0];
    const int* ei     = (const int*)d_in[1];
    const int* ea     = (const int*)d_in[2];
    const int* batch  = (const int*)d_in[3];
    const float* atom = (const float*)d_in[4];
    const float* be1  = (const float*)d_in[5];
    const float* be2  = (const float*)d_in[6];
    const float* c1_w1 = (const float*)d_in[7];
    const float* c1_b1 = (const float*)d_in[8];
    const float* c1_g  = (const float*)d_in[9];
    const float* c1_be = (const float*)d_in[10];
    const float* c1_w2 = (const float*)d_in[11];
    const float* c1_b2 = (const float*)d_in[12];
    const float* c2_w1 = (const float*)d_in[13];
    const float* c2_b1 = (const float*)d_in[14];
    const float* c2_g  = (const float*)d_in[15];
    const float* c2_be = (const float*)d_in[16];
    const float* c2_w2 = (const float*)d_in[17];
    const float* c2_b2 = (const float*)d_in[18];
    float* out = (float*)d_out;

    float *hz, *zz, *yz, *bz;
    cudaGetSymbolAddress((void**)&hz, g_h);
    cudaGetSymbolAddress((void**)&zz, g_z);
    cudaGetSymbolAddress((void**)&yz, g_y);
    cudaGetSymbolAddress((void**)&bz, g_bond);

    const int M = N_NODESC;
    const int eb = (N_EDGESC + 255) / 256;
    const int gb = (N_NODESC * 32 + 255) / 256;
    const int mtiles = (M + 127) / 128;
    dim3 gA(4, mtiles);   // Nc=512
    dim3 gB(2, mtiles);   // Nc=256

    setup_zero<<<512, 256>>>(out);
    hist<<<eb, 256>>>(ei);
    scan_offsets<<<1, 1024>>>();
    fill_csr<<<eb, 256>>>(ei, ea);
    bond_combine<<<2000, 256>>>(be1, be2);
    atom_encode<<<N_NODESC, 256>>>(x, atom);

    // ---- conv1 ----
    gather_mp<<<gb, 256>>>(bz);
    gemm_tc<false, false, 0><<<gA, 256>>>(zz, c1_w1, c1_b1, yz, M, 256, 512);
    finstats<<<2, 256>>>(c1_g, c1_be, 512, 0);
    gemm_tc<true, true, -1><<<gB, 256>>>(yz, c1_w2, c1_b2, hz, M, 512, 256);

    // ---- conv2 ----
    gather_mp<<<gb, 256>>>(bz + (size_t)1000 * DIM);
    gemm_tc<false, false, 512><<<gB, 256>>>(zz, c2_w1, c2_b1, yz, M, 256, 256);
    finstats<<<1, 256>>>(c2_g, c2_be, 256, 512);
    gemm_tc<true, true, -1><<<gB, 256>>>(yz, c2_w2, c2_b2, hz, M, 256, 256);

    // ---- pool ----
    pool_kernel<<<gb, 256>>>(batch, out);
}

// round 7
// speedup vs baseline: 3.7363x; 1.0208x over previous
#include <cuda_runtime.h>
#include <cuda_bf16.h>
#include <cstddef>
#include <cstdint>

#define N_NODESC 100000
#define N_EDGESC 3200000
#define N_GRAPHSC 2048
#define DIM 256
#define EPSC 1e-5f

// ---------------- scratch ----------------
__device__ float g_h[(size_t)N_NODESC * DIM];
__device__ float g_z[(size_t)N_NODESC * DIM];
__device__ float g_y[(size_t)N_NODESC * 2 * DIM];
__device__ float g_bond[2000 * DIM];
__device__ float g_w[393216];            // tf32-rounded weights: w1|w2|w3|w4
__device__ int   g_deg[N_NODESC + 1];
__device__ int   g_off[N_NODESC + 1];
__device__ int   g_pos[N_NODESC];
__device__ int2  g_csr[N_EDGESC];
__device__ float g_sum[1024];
__device__ float g_sq[1024];
__device__ float g_scale[512];
__device__ float g_shift[512];

__device__ __forceinline__ void red_v4(float* addr, float a, float b, float c, float d) {
    asm volatile("red.global.add.v4.f32 [%0], {%1,%2,%3,%4};"
                 :: "l"(addr), "f"(a), "f"(b), "f"(c), "f"(d) : "memory");
}
__device__ __forceinline__ float to_tf32(float x) {
    uint32_t r;
    asm("cvt.rna.tf32.f32 %0, %1;" : "=r"(r) : "f"(x));
    return __uint_as_float(r);
}
__device__ __forceinline__ void mma_tf32(float c[4], const uint32_t a[4], const uint32_t b[2]) {
    asm volatile(
        "mma.sync.aligned.m16n8k8.row.col.f32.tf32.tf32.f32 "
        "{%0,%1,%2,%3}, {%4,%5,%6,%7}, {%8,%9}, {%0,%1,%2,%3};"
        : "+f"(c[0]), "+f"(c[1]), "+f"(c[2]), "+f"(c[3])
        : "r"(a[0]), "r"(a[1]), "r"(a[2]), "r"(a[3]), "r"(b[0]), "r"(b[1]));
}
__device__ __forceinline__ void cp_async16(void* smem, const void* gmem) {
    unsigned s = (unsigned)__cvta_generic_to_shared(smem);
    asm volatile("cp.async.cg.shared.global [%0], [%1], 16;" :: "r"(s), "l"(gmem));
}
__device__ __forceinline__ void cp_commit() { asm volatile("cp.async.commit_group;"); }
__device__ __forceinline__ void cp_wait0()  { asm volatile("cp.async.wait_group 0;"); }

// ---------------- mega setup: atom encode | bond combine | out zero | weight cvt | deg hist ----
// block ranges:
//   [0, 100000)           atom encode (node = b)
//   [100000, 102000)      bond combine (b - 100000)
//   [102000, 102512)      zero out (float4)
//   [102512, 104048)      weight tf32 pre-round
//   [104048, 116548)      degree histogram (deg pre-zeroed by previous call's fill_csr)
__global__ void mega_setup(
    const int* __restrict__ x, const float* __restrict__ atom,
    const float* __restrict__ be1, const float* __restrict__ be2,
    const float* __restrict__ w1, const float* __restrict__ w2,
    const float* __restrict__ w3, const float* __restrict__ w4,
    const int* __restrict__ ei, float* __restrict__ out) {
    int b = blockIdx.x;
    int t = threadIdx.x;
    if (b < 100000) {
        __shared__ int xi[9];
        if (t < 9) xi[t] = x[b * 9 + t];
        __syncthreads();
        float s = 0.f;
#pragma unroll
        for (int c = 0; c < 9; c++) s += atom[((size_t)(c * 100 + xi[c])) * DIM + t];
        g_h[(size_t)b * DIM + t] = s;
    } else if (b < 102000) {
        int bb = b - 100000;
        const float* be = (bb < 1000) ? be1 : be2;
        int k = (bb < 1000) ? bb : bb - 1000;
        int a0 = k / 100, a1 = (k / 10) % 10, a2 = k % 10;
        g_bond[(size_t)bb * DIM + t] = be[(size_t)(0 * 10 + a0) * DIM + t]
                                     + be[(size_t)(1 * 10 + a1) * DIM + t]
                                     + be[(size_t)(2 * 10 + a2) * DIM + t];
    } else if (b < 102512) {
        int i = (b - 102000) * 256 + t;
        ((float4*)out)[i] = make_float4(0.f, 0.f, 0.f, 0.f);
    } else if (b < 104048) {
        int i = (b - 102512) * 256 + t;
        const float* src;
        int off;
        if (i < 131072)      { src = w1; off = 0; }
        else if (i < 262144) { src = w2; off = 131072; }
        else if (i < 327680) { src = w3; off = 262144; }
        else                 { src = w4; off = 327680; }
        g_w[i] = to_tf32(src[i - off]);
    } else {
        int e = (b - 104048) * 256 + t;
        if (e < N_EDGESC) atomicAdd(&g_deg[__ldg(ei + N_EDGESC + e)], 1);
    }
}

// ---------------- scan offsets (+ zero stats) ----------------
__global__ void scan_offsets() {
    const int CH = 98;
    __shared__ int ssum[1024];
    int t = threadIdx.x;
    g_sum[t] = 0.f;
    g_sq[t] = 0.f;
    int base = t * CH;
    int local = 0;
    for (int i = 0; i < CH; i++) {
        int idx = base + i;
        if (idx <= N_NODESC) local += g_deg[idx];
    }
    ssum[t] = local;
    __syncthreads();
    for (int off = 1; off < 1024; off <<= 1) {
        int v = (t >= off) ? ssum[t - off] : 0;
        __syncthreads();
        if (t >= off) ssum[t] += v;
        __syncthreads();
    }
    int run = (t == 0) ? 0 : ssum[t - 1];
    for (int i = 0; i < CH; i++) {
        int idx = base + i;
        if (idx <= N_NODESC) {
            int d = g_deg[idx];
            g_off[idx] = run;
            if (idx < N_NODESC) g_pos[idx] = run;
            run += d;
        }
    }
}

// ---------------- fill CSR (+ re-zero deg for next call; deg dead after scan) ------------
__global__ void fill_csr(const int* __restrict__ ei, const int* __restrict__ ea) {
    int e = blockIdx.x * blockDim.x + threadIdx.x;
    if (e <= N_NODESC) g_deg[e] = 0;
    if (e >= N_EDGESC) return;
    int src = __ldg(ei + e);
    int dst = __ldg(ei + N_EDGESC + e);
    int key = __ldg(ea + (size_t)e * 3 + 0) * 100
            + __ldg(ea + (size_t)e * 3 + 1) * 10
            + __ldg(ea + (size_t)e * 3 + 2);
    int slot = atomicAdd(&g_pos[dst], 1);
    g_csr[slot] = make_int2(src, key);
}

// ---------------- gather (unroll 2 for MLP) ----------------
__global__ void gather_mp(const float* __restrict__ bond) {
    int n = (int)(((size_t)blockIdx.x * blockDim.x + threadIdx.x) >> 5);
    if (n >= N_NODESC) return;
    int lane = threadIdx.x & 31;
    int f1 = lane * 4, f2 = 128 + lane * 4;
    const float* hd = g_h + (size_t)n * DIM;
    float4 a0 = *(const float4*)(hd + f1);
    float4 a1 = *(const float4*)(hd + f2);
    int p = g_off[n], pe = g_off[n + 1];
    for (; p + 2 <= pe; p += 2) {
        int2 s0 = __ldg(&g_csr[p]);
        int2 s1 = __ldg(&g_csr[p + 1]);
        const float* hs0 = g_h + (size_t)s0.x * DIM;
        const float* bs0 = bond + (size_t)s0.y * DIM;
        const float* hs1 = g_h + (size_t)s1.x * DIM;
        const float* bs1 = bond + (size_t)s1.y * DIM;
        float4 h10 = *(const float4*)(hs0 + f1);
        float4 b10 = *(const float4*)(bs0 + f1);
        float4 h20 = *(const float4*)(hs0 + f2);
        float4 b20 = *(const float4*)(bs0 + f2);
        float4 h11 = *(const float4*)(hs1 + f1);
        float4 b11 = *(const float4*)(bs1 + f1);
        float4 h21 = *(const float4*)(hs1 + f2);
        float4 b21 = *(const float4*)(bs1 + f2);
        a0.x += fmaxf(h10.x + b10.x, 0.f) + fmaxf(h11.x + b11.x, 0.f);
        a0.y += fmaxf(h10.y + b10.y, 0.f) + fmaxf(h11.y + b11.y, 0.f);
        a0.z += fmaxf(h10.z + b10.z, 0.f) + fmaxf(h11.z + b11.z, 0.f);
        a0.w += fmaxf(h10.w + b10.w, 0.f) + fmaxf(h11.w + b11.w, 0.f);
        a1.x += fmaxf(h20.x + b20.x, 0.f) + fmaxf(h21.x + b21.x, 0.f);
        a1.y += fmaxf(h20.y + b20.y, 0.f) + fmaxf(h21.y + b21.y, 0.f);
        a1.z += fmaxf(h20.z + b20.z, 0.f) + fmaxf(h21.z + b21.z, 0.f);
        a1.w += fmaxf(h20.w + b20.w, 0.f) + fmaxf(h21.w + b21.w, 0.f);
    }
    if (p < pe) {
        int2 sk = __ldg(&g_csr[p]);
        const float* hs = g_h + (size_t)sk.x * DIM;
        const float* bs = bond + (size_t)sk.y * DIM;
        float4 h1 = *(const float4*)(hs + f1);
        float4 b1 = *(const float4*)(bs + f1);
        float4 h2 = *(const float4*)(hs + f2);
        float4 b2 = *(const float4*)(bs + f2);
        a0.x += fmaxf(h1.x + b1.x, 0.f);
        a0.y += fmaxf(h1.y + b1.y, 0.f);
        a0.z += fmaxf(h1.z + b1.z, 0.f);
        a0.w += fmaxf(h1.w + b1.w, 0.f);
        a1.x += fmaxf(h2.x + b2.x, 0.f);
        a1.y += fmaxf(h2.y + b2.y, 0.f);
        a1.z += fmaxf(h2.z + b2.z, 0.f);
        a1.w += fmaxf(h2.w + b2.w, 0.f);
    }
    float* zd = g_z + (size_t)n * DIM;
    *(float4*)(zd + f1) = a0;
    *(float4*)(zd + f2) = a1;
}

// ---------------- BN finalize ----------------
__global__ void finstats(const float* __restrict__ gamma, const float* __restrict__ beta,
                         int Dh, int off) {
    int c = blockIdx.x * 256 + threadIdx.x;
    if (c >= Dh) return;
    float inv_n = 1.0f / (float)N_NODESC;
    float mu = g_sum[off + c] * inv_n;
    float var = g_sq[off + c] * inv_n - mu * mu;
    float rs = rsqrtf(var + EPSC);
    float sc = rs * gamma[c];
    g_scale[c] = sc;
    g_shift[c] = beta[c] - mu * sc;
}

// ---------------- tf32 tensor-core GEMM 128x128x16 ----------------
// B is pre-rounded to tf32 (raw cp.async). A: LDG -> (BN+ReLU) -> tf32 -> STS.
template <bool TRANSFORM, bool RELU, int STATS>
__global__ __launch_bounds__(256) void gemm_tc(
    const float* __restrict__ A, const float* __restrict__ B,
    const float* __restrict__ bias, float* __restrict__ C,
    int M, int K, int Nc) {
    const int BM = 128, BN = 128, BK = 16;
    const int BKP = BK + 4;    // A row pad (conflict-free A frags)
    const int BNP = BN + 8;    // 136: bank = 8*lr + lq -> bijection, conflict-free B frags
    __shared__ float As[2][BM][BKP];
    __shared__ float Bs[2][BK][BNP];

    int tid = threadIdx.x;
    int lane = tid & 31;
    int wid = tid >> 5;
    int wm = wid & 1;
    int wn = wid >> 1;
    int bm = blockIdx.y * BM;
    int bn = blockIdx.x * BN;

    int idx0 = tid, idx1 = tid + 256;
    int ar0 = idx0 >> 2, ak0 = (idx0 & 3) * 4;
    int ar1 = idx1 >> 2, ak1 = (idx1 & 3) * 4;
    int br0 = idx0 >> 5, bq0 = (idx0 & 31) * 4;
    int br1 = idx1 >> 5, bq1 = (idx1 & 31) * 4;
    bool aok0 = (bm + ar0) < M;
    bool aok1 = (bm + ar1) < M;

    float c[4][4][4];
#pragma unroll
    for (int mt = 0; mt < 4; mt++)
#pragma unroll
        for (int nt = 0; nt < 4; nt++)
#pragma unroll
            for (int r = 0; r < 4; r++) c[mt][nt][r] = 0.f;

    float4 a4s[2];

    auto ldg_a = [&](int k0) {
        a4s[0] = aok0 ? *(const float4*)(A + (size_t)(bm + ar0) * K + k0 + ak0)
                      : make_float4(0.f, 0.f, 0.f, 0.f);
        a4s[1] = aok1 ? *(const float4*)(A + (size_t)(bm + ar1) * K + k0 + ak1)
                      : make_float4(0.f, 0.f, 0.f, 0.f);
        if (TRANSFORM) {
#pragma unroll
            for (int t = 0; t < 2; t++) {
                int kb = k0 + ((t == 0) ? ak0 : ak1);
                float4& v = a4s[t];
                v.x = fmaxf(v.x * g_scale[kb + 0] + g_shift[kb + 0], 0.f);
                v.y = fmaxf(v.y * g_scale[kb + 1] + g_shift[kb + 1], 0.f);
                v.z = fmaxf(v.z * g_scale[kb + 2] + g_shift[kb + 2], 0.f);
                v.w = fmaxf(v.w * g_scale[kb + 3] + g_shift[kb + 3], 0.f);
            }
        }
    };
    auto sts_a = [&](int buf) {
        *(float4*)&As[buf][ar0][ak0] = make_float4(to_tf32(a4s[0].x), to_tf32(a4s[0].y),
                                                   to_tf32(a4s[0].z), to_tf32(a4s[0].w));
        *(float4*)&As[buf][ar1][ak1] = make_float4(to_tf32(a4s[1].x), to_tf32(a4s[1].y),
                                                   to_tf32(a4s[1].z), to_tf32(a4s[1].w));
    };
    auto ldb_async = [&](int buf, int k0) {
        cp_async16(&Bs[buf][br0][bq0], B + (size_t)(k0 + br0) * Nc + bn + bq0);
        cp_async16(&Bs[buf][br1][bq1], B + (size_t)(k0 + br1) * Nc + bn + bq1);
        cp_commit();
    };

    // prologue
    ldb_async(0, 0);
    ldg_a(0);
    sts_a(0);
    cp_wait0();
    __syncthreads();

    int nIter = K / BK;
    int lq = lane >> 2;
    int lr = lane & 3;
    for (int it = 0; it < nIter; it++) {
        int cur = it & 1, nxt = cur ^ 1;
        bool more = (it + 1 < nIter);
        if (more) {
            ldg_a((it + 1) * BK);
            ldb_async(nxt, (it + 1) * BK);
        }

#pragma unroll
        for (int ks = 0; ks < 2; ks++) {
            int k0 = ks * 8;
            uint32_t bf[4][2];
#pragma unroll
            for (int nt = 0; nt < 4; nt++) {
                int ncol = wn * 32 + nt * 8 + lq;
                bf[nt][0] = __float_as_uint(Bs[cur][k0 + lr][ncol]);
                bf[nt][1] = __float_as_uint(Bs[cur][k0 + 4 + lr][ncol]);
            }
#pragma unroll
            for (int mt = 0; mt < 4; mt++) {
                int mrow = wm * 64 + mt * 16 + lq;
                uint32_t af[4];
                af[0] = __float_as_uint(As[cur][mrow][k0 + lr]);
                af[1] = __float_as_uint(As[cur][mrow + 8][k0 + lr]);
                af[2] = __float_as_uint(As[cur][mrow][k0 + 4 + lr]);
                af[3] = __float_as_uint(As[cur][mrow + 8][k0 + 4 + lr]);
#pragma unroll
                for (int nt = 0; nt < 4; nt++) mma_tf32(c[mt][nt], af, bf[nt]);
            }
        }
        if (more) {
            sts_a(nxt);
            cp_wait0();
        }
        __syncthreads();
    }

    // ---------------- epilogue ----------------
    float2 bias2[4];
    int cbase[4];
#pragma unroll
    for (int nt = 0; nt < 4; nt++) {
        cbase[nt] = bn + wn * 32 + nt * 8 + lr * 2;
        bias2[nt] = *(const float2*)(bias + cbase[nt]);
    }

    float sx[4][2], qx[4][2];
    if (STATS >= 0) {
#pragma unroll
        for (int nt = 0; nt < 4; nt++) { sx[nt][0] = sx[nt][1] = 0.f; qx[nt][0] = qx[nt][1] = 0.f; }
    }

#pragma unroll
    for (int mt = 0; mt < 4; mt++) {
        int r0 = bm + wm * 64 + mt * 16 + lq;
        int r1 = r0 + 8;
        bool ok0 = r0 < M, ok1 = r1 < M;
#pragma unroll
        for (int nt = 0; nt < 4; nt++) {
            float v00 = c[mt][nt][0] + bias2[nt].x;
            float v01 = c[mt][nt][1] + bias2[nt].y;
            float v10 = c[mt][nt][2] + bias2[nt].x;
            float v11 = c[mt][nt][3] + bias2[nt].y;
            if (RELU) {
                v00 = fmaxf(v00, 0.f); v01 = fmaxf(v01, 0.f);
                v10 = fmaxf(v10, 0.f); v11 = fmaxf(v11, 0.f);
            }
            if (ok0) {
                *(float2*)(C + (size_t)r0 * Nc + cbase[nt]) = make_float2(v00, v01);
                if (STATS >= 0) {
                    sx[nt][0] += v00; sx[nt][1] += v01;
                    qx[nt][0] += v00 * v00; qx[nt][1] += v01 * v01;
                }
            }
            if (ok1) {
                *(float2*)(C + (size_t)r1 * Nc + cbase[nt]) = make_float2(v10, v11);
                if (STATS >= 0) {
                    sx[nt][0] += v10; sx[nt][1] += v11;
                    qx[nt][0] += v10 * v10; qx[nt][1] += v11 * v11;
                }
            }
        }
    }

    if (STATS >= 0) {
#pragma unroll
        for (int nt = 0; nt < 4; nt++) {
#pragma unroll
            for (int h = 0; h < 2; h++) {
#pragma unroll
                for (int off = 4; off < 32; off <<= 1) {
                    sx[nt][h] += __shfl_xor_sync(0xffffffffu, sx[nt][h], off);
                    qx[nt][h] += __shfl_xor_sync(0xffffffffu, qx[nt][h], off);
                }
            }
        }
        if (lane < 4) {
#pragma unroll
            for (int nt = 0; nt < 4; nt++) {
                atomicAdd(&g_sum[STATS + cbase[nt] + 0], sx[nt][0]);
                atomicAdd(&g_sum[STATS + cbase[nt] + 1], sx[nt][1]);
                atomicAdd(&g_sq[STATS + cbase[nt] + 0], qx[nt][0]);
                atomicAdd(&g_sq[STATS + cbase[nt] + 1], qx[nt][1]);
            }
        }
    }
}

// ---------------- global add pool ----------------
__global__ void pool_kernel(const int* __restrict__ batch, float* __restrict__ out) {
    int n = (int)(((size_t)blockIdx.x * blockDim.x + threadIdx.x) >> 5);
    if (n >= N_NODESC) return;
    int lane = threadIdx.x & 31;
    int gidx = __ldg(batch + n);
    const float* h = g_h + (size_t)n * DIM;
    float* o = out + (size_t)gidx * DIM;
#pragma unroll
    for (int i = 0; i < 2; i++) {
        int f = (lane + i * 32) * 4;
        float4 v = *(const float4*)(h + f);
        red_v4(o + f, v.x, v.y, v.z, v.w);
    }
}

// ---------------- launch ----------------
extern "C" void kernel_launch(void* const* d_in, const int* in_sizes, int n_in,
                              void* d_out, int out_size) {
    const int* x      = (const int*)d_in[0];
    const int* ei     = (const int*)d_in[1];
    const int* ea     = (const int*)d_in[2];
    const int* batch  = (const int*)d_in[3];
    const float* atom = (const float*)d_in[4];
    const float* be1  = (const float*)d_in[5];
    const float* be2  = (const float*)d_in[6];
    const float* c1_w1 = (const float*)d_in[7];
    const float* c1_b1 = (const float*)d_in[8];
    const float* c1_g  = (const float*)d_in[9];
    const float* c1_be = (const float*)d_in[10];
    const float* c1_w2 = (const float*)d_in[11];
    const float* c1_b2 = (const float*)d_in[12];
    const float* c2_w1 = (const float*)d_in[13];
    const float* c2_b1 = (const float*)d_in[14];
    const float* c2_g  = (const float*)d_in[15];
    const float* c2_be = (const float*)d_in[16];
    const float* c2_w2 = (const float*)d_in[17];
    const float* c2_b2 = (const float*)d_in[18];
    float* out = (float*)d_out;

    float *hz, *zz, *yz, *bz, *wz;
    cudaGetSymbolAddress((void**)&hz, g_h);
    cudaGetSymbolAddress((void**)&zz, g_z);
    cudaGetSymbolAddress((void**)&yz, g_y);
    cudaGetSymbolAddress((void**)&bz, g_bond);
    cudaGetSymbolAddress((void**)&wz, g_w);

    const int M = N_NODESC;
    const int eb = (N_EDGESC + 255) / 256;
    const int gb = (N_NODESC * 32 + 255) / 256;
    const int mtiles = (M + 127) / 128;
    dim3 gA(4, mtiles);   // Nc=512
    dim3 gB(2, mtiles);   // Nc=256

    // launch idx: mega(0) scan(1) fill(2) gather1(3) <- profiler samples idx 3
    mega_setup<<<116548, 256>>>(x, atom, be1, be2, c1_w1, c1_w2, c2_w1, c2_w2, ei, out);
    scan_offsets<<<1, 1024>>>();
    fill_csr<<<eb, 256>>>(ei, ea);

    // ---- conv1 ----
    gather_mp<<<gb, 256>>>(bz);
    gemm_tc<false, false, 0><<<gA, 256>>>(zz, wz + 0, c1_b1, yz, M, 256, 512);
    finstats<<<2, 256>>>(c1_g, c1_be, 512, 0);
    gemm_tc<true, true, -1><<<gB, 256>>>(yz, wz + 131072, c1_b2, hz, M, 512, 256);

    // ---- conv2 ----
    gather_mp<<<gb, 256>>>(bz + (size_t)1000 * DIM);
    gemm_tc<false, false, 512><<<gB, 256>>>(zz, wz + 262144, c2_b1, yz, M, 256, 256);
    finstats<<<1, 256>>>(c2_g, c2_be, 256, 512);
    gemm_tc<true, true, -1><<<gB, 256>>>(yz, wz + 327680, c2_b2, hz, M, 256, 256);

    // ---- pool ----
    pool_kernel<<<gb, 256>>>(batch, out);
}

// round 8
// speedup vs baseline: 4.3350x; 1.1602x over previous
#include <cuda_runtime.h>
#include <cuda_bf16.h>
#include <cstddef>
#include <cstdint>

#define N_NODESC 100000
#define N_EDGESC 3200000
#define N_GRAPHSC 2048
#define DIM 256
#define EPSC 1e-5f

// ---------------- scratch ----------------
__device__ float g_h[(size_t)N_NODESC * DIM];
__device__ float g_z[(size_t)N_NODESC * DIM];
__device__ float g_y[(size_t)N_NODESC * 2 * DIM];
__device__ __nv_bfloat16 g_hb[(size_t)N_NODESC * DIM];   // bf16 copy of h (gather operand)
__device__ __nv_bfloat16 g_bondb[2000 * DIM];            // bf16 combined bond tables
__device__ float g_w[393216];            // tf32-rounded weights: w1|w2|w3|w4
__device__ int   g_deg[N_NODESC + 1];
__device__ int   g_off[N_NODESC + 1];
__device__ int   g_pos[N_NODESC];
__device__ __align__(16) int2 g_csr[N_EDGESC];
__device__ float g_sum[1024];
__device__ float g_sq[1024];
__device__ float g_scale[512];
__device__ float g_shift[512];

__device__ __forceinline__ void red_v4(float* addr, float a, float b, float c, float d) {
    asm volatile("red.global.add.v4.f32 [%0], {%1,%2,%3,%4};"
                 :: "l"(addr), "f"(a), "f"(b), "f"(c), "f"(d) : "memory");
}
__device__ __forceinline__ float to_tf32(float x) {
    uint32_t r;
    asm("cvt.rna.tf32.f32 %0, %1;" : "=r"(r) : "f"(x));
    return __uint_as_float(r);
}
__device__ __forceinline__ void mma_tf32(float c[4], const uint32_t a[4], const uint32_t b[2]) {
    asm volatile(
        "mma.sync.aligned.m16n8k8.row.col.f32.tf32.tf32.f32 "
        "{%0,%1,%2,%3}, {%4,%5,%6,%7}, {%8,%9}, {%0,%1,%2,%3};"
        : "+f"(c[0]), "+f"(c[1]), "+f"(c[2]), "+f"(c[3])
        : "r"(a[0]), "r"(a[1]), "r"(a[2]), "r"(a[3]), "r"(b[0]), "r"(b[1]));
}
__device__ __forceinline__ void cp_async16(void* smem, const void* gmem) {
    unsigned s = (unsigned)__cvta_generic_to_shared(smem);
    asm volatile("cp.async.cg.shared.global [%0], [%1], 16;" :: "r"(s), "l"(gmem));
}
__device__ __forceinline__ void cp_commit() { asm volatile("cp.async.commit_group;"); }
__device__ __forceinline__ void cp_wait0()  { asm volatile("cp.async.wait_group 0;"); }

// accumulate relu(h+bond) for 8 bf16 features packed in uint4
__device__ __forceinline__ void acc_edge(float acc[8], uint4 h, uint4 b) {
    float2 hv, bv;
    hv = __bfloat1622float2(*(const __nv_bfloat162*)&h.x);
    bv = __bfloat1622float2(*(const __nv_bfloat162*)&b.x);
    acc[0] += fmaxf(hv.x + bv.x, 0.f); acc[1] += fmaxf(hv.y + bv.y, 0.f);
    hv = __bfloat1622float2(*(const __nv_bfloat162*)&h.y);
    bv = __bfloat1622float2(*(const __nv_bfloat162*)&b.y);
    acc[2] += fmaxf(hv.x + bv.x, 0.f); acc[3] += fmaxf(hv.y + bv.y, 0.f);
    hv = __bfloat1622float2(*(const __nv_bfloat162*)&h.z);
    bv = __bfloat1622float2(*(const __nv_bfloat162*)&b.z);
    acc[4] += fmaxf(hv.x + bv.x, 0.f); acc[5] += fmaxf(hv.y + bv.y, 0.f);
    hv = __bfloat1622float2(*(const __nv_bfloat162*)&h.w);
    bv = __bfloat1622float2(*(const __nv_bfloat162*)&b.w);
    acc[6] += fmaxf(hv.x + bv.x, 0.f); acc[7] += fmaxf(hv.y + bv.y, 0.f);
}

// ---------------- mega setup ----------------
// [0,100000) atom encode | [100000,102000) bond combine (bf16)
// [102000,102512) zero out | [102512,104048) weight cvt | rest: degree hist
__global__ void mega_setup(
    const int* __restrict__ x, const float* __restrict__ atom,
    const float* __restrict__ be1, const float* __restrict__ be2,
    const float* __restrict__ w1, const float* __restrict__ w2,
    const float* __restrict__ w3, const float* __restrict__ w4,
    const int* __restrict__ ei, float* __restrict__ out) {
    int b = blockIdx.x;
    int t = threadIdx.x;
    if (b < 100000) {
        __shared__ int xi[9];
        if (t < 9) xi[t] = x[b * 9 + t];
        __syncthreads();
        float s = 0.f;
#pragma unroll
        for (int c = 0; c < 9; c++) s += atom[((size_t)(c * 100 + xi[c])) * DIM + t];
        g_h[(size_t)b * DIM + t] = s;
        g_hb[(size_t)b * DIM + t] = __float2bfloat16(s);
    } else if (b < 102000) {
        int bb = b - 100000;
        const float* be = (bb < 1000) ? be1 : be2;
        int k = (bb < 1000) ? bb : bb - 1000;
        int a0 = k / 100, a1 = (k / 10) % 10, a2 = k % 10;
        float v = be[(size_t)(0 * 10 + a0) * DIM + t]
                + be[(size_t)(1 * 10 + a1) * DIM + t]
                + be[(size_t)(2 * 10 + a2) * DIM + t];
        g_bondb[(size_t)bb * DIM + t] = __float2bfloat16(v);
    } else if (b < 102512) {
        int i = (b - 102000) * 256 + t;
        ((float4*)out)[i] = make_float4(0.f, 0.f, 0.f, 0.f);
    } else if (b < 104048) {
        int i = (b - 102512) * 256 + t;
        const float* src;
        int off;
        if (i < 131072)      { src = w1; off = 0; }
        else if (i < 262144) { src = w2; off = 131072; }
        else if (i < 327680) { src = w3; off = 262144; }
        else                 { src = w4; off = 327680; }
        g_w[i] = to_tf32(src[i - off]);
    } else {
        int e = (b - 104048) * 256 + t;
        if (e < N_EDGESC) atomicAdd(&g_deg[__ldg(ei + N_EDGESC + e)], 1);
    }
}

// ---------------- scan offsets (+ zero stats) ----------------
__global__ void scan_offsets() {
    const int CH = 98;
    __shared__ int ssum[1024];
    int t = threadIdx.x;
    g_sum[t] = 0.f;
    g_sq[t] = 0.f;
    int base = t * CH;
    int local = 0;
    for (int i = 0; i < CH; i++) {
        int idx = base + i;
        if (idx <= N_NODESC) local += g_deg[idx];
    }
    ssum[t] = local;
    __syncthreads();
    for (int off = 1; off < 1024; off <<= 1) {
        int v = (t >= off) ? ssum[t - off] : 0;
        __syncthreads();
        if (t >= off) ssum[t] += v;
        __syncthreads();
    }
    int run = (t == 0) ? 0 : ssum[t - 1];
    for (int i = 0; i < CH; i++) {
        int idx = base + i;
        if (idx <= N_NODESC) {
            int d = g_deg[idx];
            g_off[idx] = run;
            if (idx < N_NODESC) g_pos[idx] = run;
            run += d;
        }
    }
}

// ---------------- fill CSR (+ re-zero deg for next replay) ----------------
__global__ void fill_csr(const int* __restrict__ ei, const int* __restrict__ ea) {
    int e = blockIdx.x * blockDim.x + threadIdx.x;
    if (e <= N_NODESC) g_deg[e] = 0;
    if (e >= N_EDGESC) return;
    int src = __ldg(ei + e);
    int dst = __ldg(ei + N_EDGESC + e);
    int key = __ldg(ea + (size_t)e * 3 + 0) * 100
            + __ldg(ea + (size_t)e * 3 + 1) * 10
            + __ldg(ea + (size_t)e * 3 + 2);
    int slot = atomicAdd(&g_pos[dst], 1);
    g_csr[slot] = make_int2(src, key);
}

// ---------------- gather (bf16 operands, unroll 4) ----------------
__global__ void gather_mp(const __nv_bfloat16* __restrict__ bond) {
    int n = (int)(((size_t)blockIdx.x * blockDim.x + threadIdx.x) >> 5);
    if (n >= N_NODESC) return;
    int lane = threadIdx.x & 31;
    int fo = lane * 8;                           // 8 features per lane
    const float* hd = g_h + (size_t)n * DIM + fo;
    float acc[8];
    {
        float4 s0 = *(const float4*)(hd);
        float4 s1 = *(const float4*)(hd + 4);
        acc[0] = s0.x; acc[1] = s0.y; acc[2] = s0.z; acc[3] = s0.w;
        acc[4] = s1.x; acc[5] = s1.y; acc[6] = s1.z; acc[7] = s1.w;
    }
    int p = g_off[n], pe = g_off[n + 1];
    // peel to even p for 16B-aligned int4 CSR reads
    if (p < pe && (p & 1)) {
        int2 sk = __ldg(&g_csr[p]);
        uint4 h = *(const uint4*)(g_hb + (size_t)sk.x * DIM + fo);
        uint4 b = *(const uint4*)(bond + (size_t)sk.y * DIM + fo);
        acc_edge(acc, h, b);
        p++;
    }
    for (; p + 4 <= pe; p += 4) {
        int4 e01 = *(const int4*)&g_csr[p];
        int4 e23 = *(const int4*)&g_csr[p + 2];
        uint4 h0 = *(const uint4*)(g_hb + (size_t)e01.x * DIM + fo);
        uint4 b0 = *(const uint4*)(bond + (size_t)e01.y * DIM + fo);
        uint4 h1 = *(const uint4*)(g_hb + (size_t)e01.z * DIM + fo);
        uint4 b1 = *(const uint4*)(bond + (size_t)e01.w * DIM + fo);
        uint4 h2 = *(const uint4*)(g_hb + (size_t)e23.x * DIM + fo);
        uint4 b2 = *(const uint4*)(bond + (size_t)e23.y * DIM + fo);
        uint4 h3 = *(const uint4*)(g_hb + (size_t)e23.z * DIM + fo);
        uint4 b3 = *(const uint4*)(bond + (size_t)e23.w * DIM + fo);
        acc_edge(acc, h0, b0);
        acc_edge(acc, h1, b1);
        acc_edge(acc, h2, b2);
        acc_edge(acc, h3, b3);
    }
    for (; p < pe; p++) {
        int2 sk = __ldg(&g_csr[p]);
        uint4 h = *(const uint4*)(g_hb + (size_t)sk.x * DIM + fo);
        uint4 b = *(const uint4*)(bond + (size_t)sk.y * DIM + fo);
        acc_edge(acc, h, b);
    }
    float* zd = g_z + (size_t)n * DIM + fo;
    *(float4*)(zd)     = make_float4(acc[0], acc[1], acc[2], acc[3]);
    *(float4*)(zd + 4) = make_float4(acc[4], acc[5], acc[6], acc[7]);
}

// ---------------- BN finalize ----------------
__global__ void finstats(const float* __restrict__ gamma, const float* __restrict__ beta,
                         int Dh, int off) {
    int c = blockIdx.x * 256 + threadIdx.x;
    if (c >= Dh) return;
    float inv_n = 1.0f / (float)N_NODESC;
    float mu = g_sum[off + c] * inv_n;
    float var = g_sq[off + c] * inv_n - mu * mu;
    float rs = rsqrtf(var + EPSC);
    float sc = rs * gamma[c];
    g_scale[c] = sc;
    g_shift[c] = beta[c] - mu * sc;
}

// ---------------- tf32 tensor-core GEMM 128x128x16 ----------------
// BF16OUT: also write bf16 copy of C into g_hb (gather operand for next conv).
template <bool TRANSFORM, bool RELU, int STATS, bool BF16OUT>
__global__ __launch_bounds__(256) void gemm_tc(
    const float* __restrict__ A, const float* __restrict__ B,
    const float* __restrict__ bias, float* __restrict__ C,
    int M, int K, int Nc) {
    const int BM = 128, BN = 128, BK = 16;
    const int BKP = BK + 4;
    const int BNP = BN + 8;    // conflict-free B frags
    __shared__ float As[2][BM][BKP];
    __shared__ float Bs[2][BK][BNP];

    int tid = threadIdx.x;
    int lane = tid & 31;
    int wid = tid >> 5;
    int wm = wid & 1;
    int wn = wid >> 1;
    int bm = blockIdx.y * BM;
    int bn = blockIdx.x * BN;

    int idx0 = tid, idx1 = tid + 256;
    int ar0 = idx0 >> 2, ak0 = (idx0 & 3) * 4;
    int ar1 = idx1 >> 2, ak1 = (idx1 & 3) * 4;
    int br0 = idx0 >> 5, bq0 = (idx0 & 31) * 4;
    int br1 = idx1 >> 5, bq1 = (idx1 & 31) * 4;
    bool aok0 = (bm + ar0) < M;
    bool aok1 = (bm + ar1) < M;

    float c[4][4][4];
#pragma unroll
    for (int mt = 0; mt < 4; mt++)
#pragma unroll
        for (int nt = 0; nt < 4; nt++)
#pragma unroll
            for (int r = 0; r < 4; r++) c[mt][nt][r] = 0.f;

    float4 a4s[2];

    auto ldg_a = [&](int k0) {
        a4s[0] = aok0 ? *(const float4*)(A + (size_t)(bm + ar0) * K + k0 + ak0)
                      : make_float4(0.f, 0.f, 0.f, 0.f);
        a4s[1] = aok1 ? *(const float4*)(A + (size_t)(bm + ar1) * K + k0 + ak1)
                      : make_float4(0.f, 0.f, 0.f, 0.f);
        if (TRANSFORM) {
#pragma unroll
            for (int t = 0; t < 2; t++) {
                int kb = k0 + ((t == 0) ? ak0 : ak1);
                float4& v = a4s[t];
                v.x = fmaxf(v.x * g_scale[kb + 0] + g_shift[kb + 0], 0.f);
                v.y = fmaxf(v.y * g_scale[kb + 1] + g_shift[kb + 1], 0.f);
                v.z = fmaxf(v.z * g_scale[kb + 2] + g_shift[kb + 2], 0.f);
                v.w = fmaxf(v.w * g_scale[kb + 3] + g_shift[kb + 3], 0.f);
            }
        }
    };
    auto sts_a = [&](int buf) {
        *(float4*)&As[buf][ar0][ak0] = make_float4(to_tf32(a4s[0].x), to_tf32(a4s[0].y),
                                                   to_tf32(a4s[0].z), to_tf32(a4s[0].w));
        *(float4*)&As[buf][ar1][ak1] = make_float4(to_tf32(a4s[1].x), to_tf32(a4s[1].y),
                                                   to_tf32(a4s[1].z), to_tf32(a4s[1].w));
    };
    auto ldb_async = [&](int buf, int k0) {
        cp_async16(&Bs[buf][br0][bq0], B + (size_t)(k0 + br0) * Nc + bn + bq0);
        cp_async16(&Bs[buf][br1][bq1], B + (size_t)(k0 + br1) * Nc + bn + bq1);
        cp_commit();
    };

    ldb_async(0, 0);
    ldg_a(0);
    sts_a(0);
    cp_wait0();
    __syncthreads();

    int nIter = K / BK;
    int lq = lane >> 2;
    int lr = lane & 3;
    for (int it = 0; it < nIter; it++) {
        int cur = it & 1, nxt = cur ^ 1;
        bool more = (it + 1 < nIter);
        if (more) {
            ldg_a((it + 1) * BK);
            ldb_async(nxt, (it + 1) * BK);
        }
#pragma unroll
        for (int ks = 0; ks < 2; ks++) {
            int k0 = ks * 8;
            uint32_t bf[4][2];
#pragma unroll
            for (int nt = 0; nt < 4; nt++) {
                int ncol = wn * 32 + nt * 8 + lq;
                bf[nt][0] = __float_as_uint(Bs[cur][k0 + lr][ncol]);
                bf[nt][1] = __float_as_uint(Bs[cur][k0 + 4 + lr][ncol]);
            }
#pragma unroll
            for (int mt = 0; mt < 4; mt++) {
                int mrow = wm * 64 + mt * 16 + lq;
                uint32_t af[4];
                af[0] = __float_as_uint(As[cur][mrow][k0 + lr]);
                af[1] = __float_as_uint(As[cur][mrow + 8][k0 + lr]);
                af[2] = __float_as_uint(As[cur][mrow][k0 + 4 + lr]);
                af[3] = __float_as_uint(As[cur][mrow + 8][k0 + 4 + lr]);
#pragma unroll
                for (int nt = 0; nt < 4; nt++) mma_tf32(c[mt][nt], af, bf[nt]);
            }
        }
        if (more) {
            sts_a(nxt);
            cp_wait0();
        }
        __syncthreads();
    }

    // ---------------- epilogue ----------------
    float2 bias2[4];
    int cbase[4];
#pragma unroll
    for (int nt = 0; nt < 4; nt++) {
        cbase[nt] = bn + wn * 32 + nt * 8 + lr * 2;
        bias2[nt] = *(const float2*)(bias + cbase[nt]);
    }

    float sx[4][2], qx[4][2];
    if (STATS >= 0) {
#pragma unroll
        for (int nt = 0; nt < 4; nt++) { sx[nt][0] = sx[nt][1] = 0.f; qx[nt][0] = qx[nt][1] = 0.f; }
    }

#pragma unroll
    for (int mt = 0; mt < 4; mt++) {
        int r0 = bm + wm * 64 + mt * 16 + lq;
        int r1 = r0 + 8;
        bool ok0 = r0 < M, ok1 = r1 < M;
#pragma unroll
        for (int nt = 0; nt < 4; nt++) {
            float v00 = c[mt][nt][0] + bias2[nt].x;
            float v01 = c[mt][nt][1] + bias2[nt].y;
            float v10 = c[mt][nt][2] + bias2[nt].x;
            float v11 = c[mt][nt][3] + bias2[nt].y;
            if (RELU) {
                v00 = fmaxf(v00, 0.f); v01 = fmaxf(v01, 0.f);
                v10 = fmaxf(v10, 0.f); v11 = fmaxf(v11, 0.f);
            }
            if (ok0) {
                *(float2*)(C + (size_t)r0 * Nc + cbase[nt]) = make_float2(v00, v01);
                if (BF16OUT)
                    *(__nv_bfloat162*)(g_hb + (size_t)r0 * DIM + cbase[nt]) =
                        __floats2bfloat162_rn(v00, v01);
                if (STATS >= 0) {
                    sx[nt][0] += v00; sx[nt][1] += v01;
                    qx[nt][0] += v00 * v00; qx[nt][1] += v01 * v01;
                }
            }
            if (ok1) {
                *(float2*)(C + (size_t)r1 * Nc + cbase[nt]) = make_float2(v10, v11);
                if (BF16OUT)
                    *(__nv_bfloat162*)(g_hb + (size_t)r1 * DIM + cbase[nt]) =
                        __floats2bfloat162_rn(v10, v11);
                if (STATS >= 0) {
                    sx[nt][0] += v10; sx[nt][1] += v11;
                    qx[nt][0] += v10 * v10; qx[nt][1] += v11 * v11;
                }
            }
        }
    }

    if (STATS >= 0) {
#pragma unroll
        for (int nt = 0; nt < 4; nt++) {
#pragma unroll
            for (int h = 0; h < 2; h++) {
#pragma unroll
                for (int off = 4; off < 32; off <<= 1) {
                    sx[nt][h] += __shfl_xor_sync(0xffffffffu, sx[nt][h], off);
                    qx[nt][h] += __shfl_xor_sync(0xffffffffu, qx[nt][h], off);
                }
            }
        }
        if (lane < 4) {
#pragma unroll
            for (int nt = 0; nt < 4; nt++) {
                atomicAdd(&g_sum[STATS + cbase[nt] + 0], sx[nt][0]);
                atomicAdd(&g_sum[STATS + cbase[nt] + 1], sx[nt][1]);
                atomicAdd(&g_sq[STATS + cbase[nt] + 0], qx[nt][0]);
                atomicAdd(&g_sq[STATS + cbase[nt] + 1], qx[nt][1]);
            }
        }
    }
}

// ---------------- global add pool ----------------
__global__ void pool_kernel(const int* __restrict__ batch, float* __restrict__ out) {
    int n = (int)(((size_t)blockIdx.x * blockDim.x + threadIdx.x) >> 5);
    if (n >= N_NODESC) return;
    int lane = threadIdx.x & 31;
    int gidx = __ldg(batch + n);
    const float* h = g_h + (size_t)n * DIM;
    float* o = out + (size_t)gidx * DIM;
#pragma unroll
    for (int i = 0; i < 2; i++) {
        int f = (lane + i * 32) * 4;
        float4 v = *(const float4*)(h + f);
        red_v4(o + f, v.x, v.y, v.z, v.w);
    }
}

// ---------------- launch ----------------
extern "C" void kernel_launch(void* const* d_in, const int* in_sizes, int n_in,
                              void* d_out, int out_size) {
    const int* x      = (const int*)d_in[0];
    const int* ei     = (const int*)d_in[1];
    const int* ea     = (const int*)d_in[2];
    const int* batch  = (const int*)d_in[3];
    const float* atom = (const float*)d_in[4];
    const float* be1  = (const float*)d_in[5];
    const float* be2  = (const float*)d_in[6];
    const float* c1_w1 = (const float*)d_in[7];
    const float* c1_b1 = (const float*)d_in[8];
    const float* c1_g  = (const float*)d_in[9];
    const float* c1_be = (const float*)d_in[10];
    const float* c1_w2 = (const float*)d_in[11];
    const float* c1_b2 = (const float*)d_in[12];
    const float* c2_w1 = (const float*)d_in[13];
    const float* c2_b1 = (const float*)d_in[14];
    const float* c2_g  = (const float*)d_in[15];
    const float* c2_be = (const float*)d_in[16];
    const float* c2_w2 = (const float*)d_in[17];
    const float* c2_b2 = (const float*)d_in[18];
    float* out = (float*)d_out;

    float *hz, *zz, *yz, *wz;
    __nv_bfloat16 *bbz;
    cudaGetSymbolAddress((void**)&hz, g_h);
    cudaGetSymbolAddress((void**)&zz, g_z);
    cudaGetSymbolAddress((void**)&yz, g_y);
    cudaGetSymbolAddress((void**)&wz, g_w);
    cudaGetSymbolAddress((void**)&bbz, g_bondb);

    const int M = N_NODESC;
    const int eb = (N_EDGESC + 255) / 256;
    const int gb = (N_NODESC * 32 + 255) / 256;
    const int mtiles = (M + 127) / 128;
    dim3 gA(4, mtiles);   // Nc=512
    dim3 gB(2, mtiles);   // Nc=256

    // idx: mega(0) scan(1) fill(2) gather1(3) <- ncu samples idx 3
    mega_setup<<<116548, 256>>>(x, atom, be1, be2, c1_w1, c1_w2, c2_w1, c2_w2, ei, out);
    scan_offsets<<<1, 1024>>>();
    fill_csr<<<eb, 256>>>(ei, ea);

    // ---- conv1 ----
    gather_mp<<<gb, 256>>>(bbz);
    gemm_tc<false, false, 0, false><<<gA, 256>>>(zz, wz + 0, c1_b1, yz, M, 256, 512);
    finstats<<<2, 256>>>(c1_g, c1_be, 512, 0);
    gemm_tc<true, true, -1, true><<<gB, 256>>>(yz, wz + 131072, c1_b2, hz, M, 512, 256);

    // ---- conv2 ----
    gather_mp<<<gb, 256>>>(bbz + (size_t)1000 * DIM);
    gemm_tc<false, false, 512, false><<<gB, 256>>>(zz, wz + 262144, c2_b1, yz, M, 256, 256);
    finstats<<<1, 256>>>(c2_g, c2_be, 256, 512);
    gemm_tc<true, true, -1, false><<<gB, 256>>>(yz, wz + 327680, c2_b2, hz, M, 256, 256);

    // ---- pool ----
    pool_kernel<<<gb, 256>>>(batch, out);
}

// round 9
// speedup vs baseline: 4.7146x; 1.0876x over previous
#include <cuda_runtime.h>
#include <cuda_bf16.h>
#include <cstddef>
#include <cstdint>

#define N_NODESC 100000
#define N_EDGESC 3200000
#define N_GRAPHSC 2048
#define DIM 256
#define EPSC 1e-5f

// ---------------- scratch ----------------
__device__ float g_h[(size_t)N_NODESC * DIM];
__device__ float g_z[(size_t)N_NODESC * DIM];
__device__ float g_y[(size_t)N_NODESC * 2 * DIM];
__device__ __nv_bfloat16 g_hb[(size_t)N_NODESC * DIM];   // bf16 copy of h (gather operand)
__device__ __nv_bfloat16 g_bondb[2000 * DIM];            // bf16 combined bond tables
__device__ float g_w[393216];            // tf32-rounded weights: w1|w2|w3|w4
__device__ int   g_deg[N_NODESC + 1];
__device__ int   g_off[N_NODESC + 1];
__device__ int   g_pos[N_NODESC];
__device__ __align__(16) int2 g_csr[N_EDGESC];
__device__ float g_sum[1024];
__device__ float g_sq[1024];
__device__ float g_scale[512];
__device__ float g_shift[512];

__device__ __forceinline__ void red_v4(float* addr, float a, float b, float c, float d) {
    asm volatile("red.global.add.v4.f32 [%0], {%1,%2,%3,%4};"
                 :: "l"(addr), "f"(a), "f"(b), "f"(c), "f"(d) : "memory");
}
__device__ __forceinline__ float to_tf32(float x) {
    uint32_t r;
    asm("cvt.rna.tf32.f32 %0, %1;" : "=r"(r) : "f"(x));
    return __uint_as_float(r);
}
__device__ __forceinline__ void mma_tf32(float c[4], const uint32_t a[4], const uint32_t b[2]) {
    asm volatile(
        "mma.sync.aligned.m16n8k8.row.col.f32.tf32.tf32.f32 "
        "{%0,%1,%2,%3}, {%4,%5,%6,%7}, {%8,%9}, {%0,%1,%2,%3};"
        : "+f"(c[0]), "+f"(c[1]), "+f"(c[2]), "+f"(c[3])
        : "r"(a[0]), "r"(a[1]), "r"(a[2]), "r"(a[3]), "r"(b[0]), "r"(b[1]));
}
__device__ __forceinline__ void cp_async16(void* smem, const void* gmem) {
    unsigned s = (unsigned)__cvta_generic_to_shared(smem);
    asm volatile("cp.async.cg.shared.global [%0], [%1], 16;" :: "r"(s), "l"(gmem));
}
__device__ __forceinline__ void cp_commit() { asm volatile("cp.async.commit_group;"); }
__device__ __forceinline__ void cp_wait0()  { asm volatile("cp.async.wait_group 0;"); }

// accumulate relu(h+bond) for 8 bf16 features packed in uint4 — bf16x2 SIMD math,
// fp32 accumulation. relu in bf16 is exact; only the h+b add rounds.
__device__ __forceinline__ void acc_edge(float acc[8], uint4 h, uint4 b) {
    const __nv_bfloat162 z2 = __float2bfloat162_rn(0.f);
    __nv_bfloat162 m;
    float2 v;
    m = __hmax2(__hadd2(*(const __nv_bfloat162*)&h.x, *(const __nv_bfloat162*)&b.x), z2);
    v = __bfloat1622float2(m); acc[0] += v.x; acc[1] += v.y;
    m = __hmax2(__hadd2(*(const __nv_bfloat162*)&h.y, *(const __nv_bfloat162*)&b.y), z2);
    v = __bfloat1622float2(m); acc[2] += v.x; acc[3] += v.y;
    m = __hmax2(__hadd2(*(const __nv_bfloat162*)&h.z, *(const __nv_bfloat162*)&b.z), z2);
    v = __bfloat1622float2(m); acc[4] += v.x; acc[5] += v.y;
    m = __hmax2(__hadd2(*(const __nv_bfloat162*)&h.w, *(const __nv_bfloat162*)&b.w), z2);
    v = __bfloat1622float2(m); acc[6] += v.x; acc[7] += v.y;
}

// ---------------- mega setup ----------------
// [0,25000)       atom encode, 4 nodes per block, float4 per thread
// [25000,27000)   bond combine (bf16)
// [27000,27512)   zero out
// [27512,29048)   weight tf32 pre-round
// [29048,41548)   degree histogram (deg pre-zeroed by previous call's fill_csr)
__global__ void mega_setup(
    const int* __restrict__ x, const float* __restrict__ atom,
    const float* __restrict__ be1, const float* __restrict__ be2,
    const float* __restrict__ w1, const float* __restrict__ w2,
    const float* __restrict__ w3, const float* __restrict__ w4,
    const int* __restrict__ ei, float* __restrict__ out) {
    int b = blockIdx.x;
    int t = threadIdx.x;
    if (b < 25000) {
        __shared__ int xi[4][9];
        if (t < 36) xi[t / 9][t % 9] = x[(b * 4 + t / 9) * 9 + (t % 9)];
        __syncthreads();
        int sub = t >> 6;
        int fg = (t & 63) * 4;
        size_t node = (size_t)b * 4 + sub;
        float4 s = make_float4(0.f, 0.f, 0.f, 0.f);
#pragma unroll
        for (int c = 0; c < 9; c++) {
            float4 v = *(const float4*)(atom + ((size_t)(c * 100 + xi[sub][c])) * DIM + fg);
            s.x += v.x; s.y += v.y; s.z += v.z; s.w += v.w;
        }
        *(float4*)(g_h + node * DIM + fg) = s;
        uint2 packed;
        *(__nv_bfloat162*)&packed.x = __floats2bfloat162_rn(s.x, s.y);
        *(__nv_bfloat162*)&packed.y = __floats2bfloat162_rn(s.z, s.w);
        *(uint2*)(g_hb + node * DIM + fg) = packed;
    } else if (b < 27000) {
        int bb = b - 25000;
        const float* be = (bb < 1000) ? be1 : be2;
        int k = (bb < 1000) ? bb : bb - 1000;
        int a0 = k / 100, a1 = (k / 10) % 10, a2 = k % 10;
        float v = be[(size_t)(0 * 10 + a0) * DIM + t]
                + be[(size_t)(1 * 10 + a1) * DIM + t]
                + be[(size_t)(2 * 10 + a2) * DIM + t];
        g_bondb[(size_t)bb * DIM + t] = __float2bfloat16(v);
    } else if (b < 27512) {
        int i = (b - 27000) * 256 + t;
        ((float4*)out)[i] = make_float4(0.f, 0.f, 0.f, 0.f);
    } else if (b < 29048) {
        int i = (b - 27512) * 256 + t;
        const float* src;
        int off;
        if (i < 131072)      { src = w1; off = 0; }
        else if (i < 262144) { src = w2; off = 131072; }
        else if (i < 327680) { src = w3; off = 262144; }
        else                 { src = w4; off = 327680; }
        g_w[i] = to_tf32(src[i - off]);
    } else {
        int e = (b - 29048) * 256 + t;
        if (e < N_EDGESC) atomicAdd(&g_deg[__ldg(ei + N_EDGESC + e)], 1);
    }
}

// ---------------- scan offsets (+ zero stats) ----------------
__global__ void scan_offsets() {
    const int CH = 98;
    __shared__ int ssum[1024];
    int t = threadIdx.x;
    g_sum[t] = 0.f;
    g_sq[t] = 0.f;
    int base = t * CH;
    int local = 0;
    for (int i = 0; i < CH; i++) {
        int idx = base + i;
        if (idx <= N_NODESC) local += g_deg[idx];
    }
    ssum[t] = local;
    __syncthreads();
    for (int off = 1; off < 1024; off <<= 1) {
        int v = (t >= off) ? ssum[t - off] : 0;
        __syncthreads();
        if (t >= off) ssum[t] += v;
        __syncthreads();
    }
    int run = (t == 0) ? 0 : ssum[t - 1];
    for (int i = 0; i < CH; i++) {
        int idx = base + i;
        if (idx <= N_NODESC) {
            int d = g_deg[idx];
            g_off[idx] = run;
            if (idx < N_NODESC) g_pos[idx] = run;
            run += d;
        }
    }
}

// ---------------- fill CSR (+ re-zero deg for next replay) ----------------
__global__ void fill_csr(const int* __restrict__ ei, const int* __restrict__ ea) {
    int e = blockIdx.x * blockDim.x + threadIdx.x;
    if (e <= N_NODESC) g_deg[e] = 0;
    if (e >= N_EDGESC) return;
    int src = __ldg(ei + e);
    int dst = __ldg(ei + N_EDGESC + e);
    int key = __ldg(ea + (size_t)e * 3 + 0) * 100
            + __ldg(ea + (size_t)e * 3 + 1) * 10
            + __ldg(ea + (size_t)e * 3 + 2);
    int slot = atomicAdd(&g_pos[dst], 1);
    g_csr[slot] = make_int2(src, key);
}

// ---------------- gather (bf16x2 SIMD, unroll 4) ----------------
__global__ void gather_mp(const __nv_bfloat16* __restrict__ bond) {
    int n = (int)(((size_t)blockIdx.x * blockDim.x + threadIdx.x) >> 5);
    if (n >= N_NODESC) return;
    int lane = threadIdx.x & 31;
    int fo = lane * 8;
    const float* hd = g_h + (size_t)n * DIM + fo;
    float acc[8];
    {
        float4 s0 = *(const float4*)(hd);
        float4 s1 = *(const float4*)(hd + 4);
        acc[0] = s0.x; acc[1] = s0.y; acc[2] = s0.z; acc[3] = s0.w;
        acc[4] = s1.x; acc[5] = s1.y; acc[6] = s1.z; acc[7] = s1.w;
    }
    int p = g_off[n], pe = g_off[n + 1];
    if (p < pe && (p & 1)) {
        int2 sk = __ldg(&g_csr[p]);
        uint4 h = *(const uint4*)(g_hb + (size_t)sk.x * DIM + fo);
        uint4 b = *(const uint4*)(bond + (size_t)sk.y * DIM + fo);
        acc_edge(acc, h, b);
        p++;
    }
    for (; p + 4 <= pe; p += 4) {
        int4 e01 = *(const int4*)&g_csr[p];
        int4 e23 = *(const int4*)&g_csr[p + 2];
        uint4 h0 = *(const uint4*)(g_hb + (size_t)e01.x * DIM + fo);
        uint4 b0 = *(const uint4*)(bond + (size_t)e01.y * DIM + fo);
        uint4 h1 = *(const uint4*)(g_hb + (size_t)e01.z * DIM + fo);
        uint4 b1 = *(const uint4*)(bond + (size_t)e01.w * DIM + fo);
        uint4 h2 = *(const uint4*)(g_hb + (size_t)e23.x * DIM + fo);
        uint4 b2 = *(const uint4*)(bond + (size_t)e23.y * DIM + fo);
        uint4 h3 = *(const uint4*)(g_hb + (size_t)e23.z * DIM + fo);
        uint4 b3 = *(const uint4*)(bond + (size_t)e23.w * DIM + fo);
        acc_edge(acc, h0, b0);
        acc_edge(acc, h1, b1);
        acc_edge(acc, h2, b2);
        acc_edge(acc, h3, b3);
    }
    for (; p < pe; p++) {
        int2 sk = __ldg(&g_csr[p]);
        uint4 h = *(const uint4*)(g_hb + (size_t)sk.x * DIM + fo);
        uint4 b = *(const uint4*)(bond + (size_t)sk.y * DIM + fo);
        acc_edge(acc, h, b);
    }
    float* zd = g_z + (size_t)n * DIM + fo;
    *(float4*)(zd)     = make_float4(acc[0], acc[1], acc[2], acc[3]);
    *(float4*)(zd + 4) = make_float4(acc[4], acc[5], acc[6], acc[7]);
}

// ---------------- BN finalize ----------------
__global__ void finstats(const float* __restrict__ gamma, const float* __restrict__ beta,
                         int Dh, int off) {
    int c = blockIdx.x * 256 + threadIdx.x;
    if (c >= Dh) return;
    float inv_n = 1.0f / (float)N_NODESC;
    float mu = g_sum[off + c] * inv_n;
    float var = g_sq[off + c] * inv_n - mu * mu;
    float rs = rsqrtf(var + EPSC);
    float sc = rs * gamma[c];
    g_scale[c] = sc;
    g_shift[c] = beta[c] - mu * sc;
}

// ---------------- tf32 tensor-core GEMM 128x128x16 ----------------
template <bool TRANSFORM, bool RELU, int STATS, bool BF16OUT>
__global__ __launch_bounds__(256) void gemm_tc(
    const float* __restrict__ A, const float* __restrict__ B,
    const float* __restrict__ bias, float* __restrict__ C,
    int M, int K, int Nc) {
    const int BM = 128, BN = 128, BK = 16;
    const int BKP = BK + 4;
    const int BNP = BN + 8;
    __shared__ float As[2][BM][BKP];
    __shared__ float Bs[2][BK][BNP];

    int tid = threadIdx.x;
    int lane = tid & 31;
    int wid = tid >> 5;
    int wm = wid & 1;
    int wn = wid >> 1;
    int bm = blockIdx.y * BM;
    int bn = blockIdx.x * BN;

    int idx0 = tid, idx1 = tid + 256;
    int ar0 = idx0 >> 2, ak0 = (idx0 & 3) * 4;
    int ar1 = idx1 >> 2, ak1 = (idx1 & 3) * 4;
    int br0 = idx0 >> 5, bq0 = (idx0 & 31) * 4;
    int br1 = idx1 >> 5, bq1 = (idx1 & 31) * 4;
    bool aok0 = (bm + ar0) < M;
    bool aok1 = (bm + ar1) < M;

    float c[4][4][4];
#pragma unroll
    for (int mt = 0; mt < 4; mt++)
#pragma unroll
        for (int nt = 0; nt < 4; nt++)
#pragma unroll
            for (int r = 0; r < 4; r++) c[mt][nt][r] = 0.f;

    float4 a4s[2];

    auto ldg_a = [&](int k0) {
        a4s[0] = aok0 ? *(const float4*)(A + (size_t)(bm + ar0) * K + k0 + ak0)
                      : make_float4(0.f, 0.f, 0.f, 0.f);
        a4s[1] = aok1 ? *(const float4*)(A + (size_t)(bm + ar1) * K + k0 + ak1)
                      : make_float4(0.f, 0.f, 0.f, 0.f);
        if (TRANSFORM) {
#pragma unroll
            for (int t = 0; t < 2; t++) {
                int kb = k0 + ((t == 0) ? ak0 : ak1);
                float4& v = a4s[t];
                v.x = fmaxf(v.x * g_scale[kb + 0] + g_shift[kb + 0], 0.f);
                v.y = fmaxf(v.y * g_scale[kb + 1] + g_shift[kb + 1], 0.f);
                v.z = fmaxf(v.z * g_scale[kb + 2] + g_shift[kb + 2], 0.f);
                v.w = fmaxf(v.w * g_scale[kb + 3] + g_shift[kb + 3], 0.f);
            }
        }
    };
    auto sts_a = [&](int buf) {
        *(float4*)&As[buf][ar0][ak0] = make_float4(to_tf32(a4s[0].x), to_tf32(a4s[0].y),
                                                   to_tf32(a4s[0].z), to_tf32(a4s[0].w));
        *(float4*)&As[buf][ar1][ak1] = make_float4(to_tf32(a4s[1].x), to_tf32(a4s[1].y),
                                                   to_tf32(a4s[1].z), to_tf32(a4s[1].w));
    };
    auto ldb_async = [&](int buf, int k0) {
        cp_async16(&Bs[buf][br0][bq0], B + (size_t)(k0 + br0) * Nc + bn + bq0);
        cp_async16(&Bs[buf][br1][bq1], B + (size_t)(k0 + br1) * Nc + bn + bq1);
        cp_commit();
    };

    ldb_async(0, 0);
    ldg_a(0);
    sts_a(0);
    cp_wait0();
    __syncthreads();

    int nIter = K / BK;
    int lq = lane >> 2;
    int lr = lane & 3;
    for (int it = 0; it < nIter; it++) {
        int cur = it & 1, nxt = cur ^ 1;
        bool more = (it + 1 < nIter);
        if (more) {
            ldg_a((it + 1) * BK);
            ldb_async(nxt, (it + 1) * BK);
        }
#pragma unroll
        for (int ks = 0; ks < 2; ks++) {
            int k0 = ks * 8;
            uint32_t bf[4][2];
#pragma unroll
            for (int nt = 0; nt < 4; nt++) {
                int ncol = wn * 32 + nt * 8 + lq;
                bf[nt][0] = __float_as_uint(Bs[cur][k0 + lr][ncol]);
                bf[nt][1] = __float_as_uint(Bs[cur][k0 + 4 + lr][ncol]);
            }
#pragma unroll
            for (int mt = 0; mt < 4; mt++) {
                int mrow = wm * 64 + mt * 16 + lq;
                uint32_t af[4];
                af[0] = __float_as_uint(As[cur][mrow][k0 + lr]);
                af[1] = __float_as_uint(As[cur][mrow + 8][k0 + lr]);
                af[2] = __float_as_uint(As[cur][mrow][k0 + 4 + lr]);
                af[3] = __float_as_uint(As[cur][mrow + 8][k0 + 4 + lr]);
#pragma unroll
                for (int nt = 0; nt < 4; nt++) mma_tf32(c[mt][nt], af, bf[nt]);
            }
        }
        if (more) {
            sts_a(nxt);
            cp_wait0();
        }
        __syncthreads();
    }

    // ---------------- epilogue ----------------
    float2 bias2[4];
    int cbase[4];
#pragma unroll
    for (int nt = 0; nt < 4; nt++) {
        cbase[nt] = bn + wn * 32 + nt * 8 + lr * 2;
        bias2[nt] = *(const float2*)(bias + cbase[nt]);
    }

    float sx[4][2], qx[4][2];
    if (STATS >= 0) {
#pragma unroll
        for (int nt = 0; nt < 4; nt++) { sx[nt][0] = sx[nt][1] = 0.f; qx[nt][0] = qx[nt][1] = 0.f; }
    }

#pragma unroll
    for (int mt = 0; mt < 4; mt++) {
        int r0 = bm + wm * 64 + mt * 16 + lq;
        int r1 = r0 + 8;
        bool ok0 = r0 < M, ok1 = r1 < M;
#pragma unroll
        for (int nt = 0; nt < 4; nt++) {
            float v00 = c[mt][nt][0] + bias2[nt].x;
            float v01 = c[mt][nt][1] + bias2[nt].y;
            float v10 = c[mt][nt][2] + bias2[nt].x;
            float v11 = c[mt][nt][3] + bias2[nt].y;
            if (RELU) {
                v00 = fmaxf(v00, 0.f); v01 = fmaxf(v01, 0.f);
                v10 = fmaxf(v10, 0.f); v11 = fmaxf(v11, 0.f);
            }
            if (ok0) {
                *(float2*)(C + (size_t)r0 * Nc + cbase[nt]) = make_float2(v00, v01);
                if (BF16OUT)
                    *(__nv_bfloat162*)(g_hb + (size_t)r0 * DIM + cbase[nt]) =
                        __floats2bfloat162_rn(v00, v01);
                if (STATS >= 0) {
                    sx[nt][0] += v00; sx[nt][1] += v01;
                    qx[nt][0] += v00 * v00; qx[nt][1] += v01 * v01;
                }
            }
            if (ok1) {
                *(float2*)(C + (size_t)r1 * Nc + cbase[nt]) = make_float2(v10, v11);
                if (BF16OUT)
                    *(__nv_bfloat162*)(g_hb + (size_t)r1 * DIM + cbase[nt]) =
                        __floats2bfloat162_rn(v10, v11);
                if (STATS >= 0) {
                    sx[nt][0] += v10; sx[nt][1] += v11;
                    qx[nt][0] += v10 * v10; qx[nt][1] += v11 * v11;
                }
            }
        }
    }

    if (STATS >= 0) {
#pragma unroll
        for (int nt = 0; nt < 4; nt++) {
#pragma unroll
            for (int h = 0; h < 2; h++) {
#pragma unroll
                for (int off = 4; off < 32; off <<= 1) {
                    sx[nt][h] += __shfl_xor_sync(0xffffffffu, sx[nt][h], off);
                    qx[nt][h] += __shfl_xor_sync(0xffffffffu, qx[nt][h], off);
                }
            }
        }
        if (lane < 4) {
#pragma unroll
            for (int nt = 0; nt < 4; nt++) {
                atomicAdd(&g_sum[STATS + cbase[nt] + 0], sx[nt][0]);
                atomicAdd(&g_sum[STATS + cbase[nt] + 1], sx[nt][1]);
                atomicAdd(&g_sq[STATS + cbase[nt] + 0], qx[nt][0]);
                atomicAdd(&g_sq[STATS + cbase[nt] + 1], qx[nt][1]);
            }
        }
    }
}

// ---------------- global add pool ----------------
__global__ void pool_kernel(const int* __restrict__ batch, float* __restrict__ out) {
    int n = (int)(((size_t)blockIdx.x * blockDim.x + threadIdx.x) >> 5);
    if (n >= N_NODESC) return;
    int lane = threadIdx.x & 31;
    int gidx = __ldg(batch + n);
    const float* h = g_h + (size_t)n * DIM;
    float* o = out + (size_t)gidx * DIM;
#pragma unroll
    for (int i = 0; i < 2; i++) {
        int f = (lane + i * 32) * 4;
        float4 v = *(const float4*)(h + f);
        red_v4(o + f, v.x, v.y, v.z, v.w);
    }
}

// ---------------- launch ----------------
extern "C" void kernel_launch(void* const* d_in, const int* in_sizes, int n_in,
                              void* d_out, int out_size) {
    const int* x      = (const int*)d_in[0];
    const int* ei     = (const int*)d_in[1];
    const int* ea     = (const int*)d_in[2];
    const int* batch  = (const int*)d_in[3];
    const float* atom = (const float*)d_in[4];
    const float* be1  = (const float*)d_in[5];
    const float* be2  = (const float*)d_in[6];
    const float* c1_w1 = (const float*)d_in[7];
    const float* c1_b1 = (const float*)d_in[8];
    const float* c1_g  = (const float*)d_in[9];
    const float* c1_be = (const float*)d_in[10];
    const float* c1_w2 = (const float*)d_in[11];
    const float* c1_b2 = (const float*)d_in[12];
    const float* c2_w1 = (const float*)d_in[13];
    const float* c2_b1 = (const float*)d_in[14];
    const float* c2_g  = (const float*)d_in[15];
    const float* c2_be = (const float*)d_in[16];
    const float* c2_w2 = (const float*)d_in[17];
    const float* c2_b2 = (const float*)d_in[18];
    float* out = (float*)d_out;

    float *hz, *zz, *yz, *wz;
    __nv_bfloat16 *bbz;
    cudaGetSymbolAddress((void**)&hz, g_h);
    cudaGetSymbolAddress((void**)&zz, g_z);
    cudaGetSymbolAddress((void**)&yz, g_y);
    cudaGetSymbolAddress((void**)&wz, g_w);
    cudaGetSymbolAddress((void**)&bbz, g_bondb);

    const int M = N_NODESC;
    const int eb = (N_EDGESC + 255) / 256;
    const int gb = (N_NODESC * 32 + 255) / 256;
    const int mtiles = (M + 127) / 128;
    dim3 gA(4, mtiles);   // Nc=512
    dim3 gB(2, mtiles);   // Nc=256

    // idx: mega(0) scan(1) fill(2) gather1(3) <- ncu samples idx 3
    mega_setup<<<41548, 256>>>(x, atom, be1, be2, c1_w1, c1_w2, c2_w1, c2_w2, ei, out);
    scan_offsets<<<1, 1024>>>();
    fill_csr<<<eb, 256>>>(ei, ea);

    // ---- conv1 ----
    gather_mp<<<gb, 256>>>(bbz);
    gemm_tc<false, false, 0, false><<<gA, 256>>>(zz, wz + 0, c1_b1, yz, M, 256, 512);
    finstats<<<2, 256>>>(c1_g, c1_be, 512, 0);
    gemm_tc<true, true, -1, true><<<gB, 256>>>(yz, wz + 131072, c1_b2, hz, M, 512, 256);

    // ---- conv2 ----
    gather_mp<<<gb, 256>>>(bbz + (size_t)1000 * DIM);
    gemm_tc<false, false, 512, false><<<gB, 256>>>(zz, wz + 262144, c2_b1, yz, M, 256, 256);
    finstats<<<1, 256>>>(c2_g, c2_be, 256, 512);
    gemm_tc<true, true, -1, false><<<gB, 256>>>(yz, wz + 327680, c2_b2, hz, M, 256, 256);

    // ---- pool ----
    pool_kernel<<<gb, 256>>>(batch, out);
}

// round 10
// speedup vs baseline: 4.9249x; 1.0446x over previous
#include <cuda_runtime.h>
#include <cuda_bf16.h>
#include <cstddef>
#include <cstdint>

#define N_NODESC 100000
#define N_EDGESC 3200000
#define N_GRAPHSC 2048
#define DIM 256
#define EPSC 1e-5f

// ---------------- scratch ----------------
__device__ float g_z[(size_t)N_NODESC * DIM];
__device__ float g_y[(size_t)N_NODESC * 2 * DIM];
__device__ __nv_bfloat16 g_hb[(size_t)N_NODESC * DIM];   // bf16 node features (sole h storage)
__device__ __nv_bfloat16 g_bondb[2000 * DIM];            // bf16 combined bond tables
__device__ float g_w[393216];            // tf32-rounded weights: w1|w2|w3|w4
__device__ int   g_deg[N_NODESC + 1];
__device__ int   g_off[N_NODESC + 1];
__device__ int   g_pos[N_NODESC];
__device__ __align__(16) int2 g_csr[N_EDGESC];
__device__ float g_sum[1024];
__device__ float g_sq[1024];
__device__ float g_scale[512];
__device__ float g_shift[512];

__device__ __forceinline__ void red_v2(float* addr, float a, float b) {
    asm volatile("red.global.add.v2.f32 [%0], {%1,%2};"
                 :: "l"(addr), "f"(a), "f"(b) : "memory");
}
__device__ __forceinline__ float to_tf32(float x) {
    uint32_t r;
    asm("cvt.rna.tf32.f32 %0, %1;" : "=r"(r) : "f"(x));
    return __uint_as_float(r);
}
__device__ __forceinline__ void mma_tf32(float c[4], const uint32_t a[4], const uint32_t b[2]) {
    asm volatile(
        "mma.sync.aligned.m16n8k8.row.col.f32.tf32.tf32.f32 "
        "{%0,%1,%2,%3}, {%4,%5,%6,%7}, {%8,%9}, {%0,%1,%2,%3};"
        : "+f"(c[0]), "+f"(c[1]), "+f"(c[2]), "+f"(c[3])
        : "r"(a[0]), "r"(a[1]), "r"(a[2]), "r"(a[3]), "r"(b[0]), "r"(b[1]));
}
__device__ __forceinline__ void cp_async16(void* smem, const void* gmem) {
    unsigned s = (unsigned)__cvta_generic_to_shared(smem);
    asm volatile("cp.async.cg.shared.global [%0], [%1], 16;" :: "r"(s), "l"(gmem));
}
__device__ __forceinline__ void cp_commit() { asm volatile("cp.async.commit_group;"); }
__device__ __forceinline__ void cp_wait0()  { asm volatile("cp.async.wait_group 0;"); }

// accumulate relu(h+bond) for 8 bf16 features packed in uint4 — bf16x2 SIMD math,
// fp32 accumulation.
__device__ __forceinline__ void acc_edge(float acc[8], uint4 h, uint4 b) {
    const __nv_bfloat162 z2 = __float2bfloat162_rn(0.f);
    __nv_bfloat162 m;
    float2 v;
    m = __hmax2(__hadd2(*(const __nv_bfloat162*)&h.x, *(const __nv_bfloat162*)&b.x), z2);
    v = __bfloat1622float2(m); acc[0] += v.x; acc[1] += v.y;
    m = __hmax2(__hadd2(*(const __nv_bfloat162*)&h.y, *(const __nv_bfloat162*)&b.y), z2);
    v = __bfloat1622float2(m); acc[2] += v.x; acc[3] += v.y;
    m = __hmax2(__hadd2(*(const __nv_bfloat162*)&h.z, *(const __nv_bfloat162*)&b.z), z2);
    v = __bfloat1622float2(m); acc[4] += v.x; acc[5] += v.y;
    m = __hmax2(__hadd2(*(const __nv_bfloat162*)&h.w, *(const __nv_bfloat162*)&b.w), z2);
    v = __bfloat1622float2(m); acc[6] += v.x; acc[7] += v.y;
}

// ---------------- mega setup ----------------
// [0,25000)       atom encode -> g_hb only (4 nodes/block, float4/thread)
// [25000,27000)   bond combine (bf16)
// [27000,27512)   zero out
// [27512,29048)   weight tf32 pre-round
// [29048,41548)   degree histogram (deg pre-zeroed by previous call's fill_csr)
__global__ void mega_setup(
    const int* __restrict__ x, const float* __restrict__ atom,
    const float* __restrict__ be1, const float* __restrict__ be2,
    const float* __restrict__ w1, const float* __restrict__ w2,
    const float* __restrict__ w3, const float* __restrict__ w4,
    const int* __restrict__ ei, float* __restrict__ out) {
    int b = blockIdx.x;
    int t = threadIdx.x;
    if (b < 25000) {
        __shared__ int xi[4][9];
        if (t < 36) xi[t / 9][t % 9] = x[(b * 4 + t / 9) * 9 + (t % 9)];
        __syncthreads();
        int sub = t >> 6;
        int fg = (t & 63) * 4;
        size_t node = (size_t)b * 4 + sub;
        float4 s = make_float4(0.f, 0.f, 0.f, 0.f);
#pragma unroll
        for (int c = 0; c < 9; c++) {
            float4 v = *(const float4*)(atom + ((size_t)(c * 100 + xi[sub][c])) * DIM + fg);
            s.x += v.x; s.y += v.y; s.z += v.z; s.w += v.w;
        }
        uint2 packed;
        *(__nv_bfloat162*)&packed.x = __floats2bfloat162_rn(s.x, s.y);
        *(__nv_bfloat162*)&packed.y = __floats2bfloat162_rn(s.z, s.w);
        *(uint2*)(g_hb + node * DIM + fg) = packed;
    } else if (b < 27000) {
        int bb = b - 25000;
        const float* be = (bb < 1000) ? be1 : be2;
        int k = (bb < 1000) ? bb : bb - 1000;
        int a0 = k / 100, a1 = (k / 10) % 10, a2 = k % 10;
        float v = be[(size_t)(0 * 10 + a0) * DIM + t]
                + be[(size_t)(1 * 10 + a1) * DIM + t]
                + be[(size_t)(2 * 10 + a2) * DIM + t];
        g_bondb[(size_t)bb * DIM + t] = __float2bfloat16(v);
    } else if (b < 27512) {
        int i = (b - 27000) * 256 + t;
        ((float4*)out)[i] = make_float4(0.f, 0.f, 0.f, 0.f);
    } else if (b < 29048) {
        int i = (b - 27512) * 256 + t;
        const float* src;
        int off;
        if (i < 131072)      { src = w1; off = 0; }
        else if (i < 262144) { src = w2; off = 131072; }
        else if (i < 327680) { src = w3; off = 262144; }
        else                 { src = w4; off = 327680; }
        g_w[i] = to_tf32(src[i - off]);
    } else {
        int e = (b - 29048) * 256 + t;
        if (e < N_EDGESC) atomicAdd(&g_deg[__ldg(ei + N_EDGESC + e)], 1);
    }
}

// ---------------- scan offsets (+ zero stats) ----------------
__global__ void scan_offsets() {
    const int CH = 98;
    __shared__ int ssum[1024];
    int t = threadIdx.x;
    g_sum[t] = 0.f;
    g_sq[t] = 0.f;
    int base = t * CH;
    int local = 0;
    for (int i = 0; i < CH; i++) {
        int idx = base + i;
        if (idx <= N_NODESC) local += g_deg[idx];
    }
    ssum[t] = local;
    __syncthreads();
    for (int off = 1; off < 1024; off <<= 1) {
        int v = (t >= off) ? ssum[t - off] : 0;
        __syncthreads();
        if (t >= off) ssum[t] += v;
        __syncthreads();
    }
    int run = (t == 0) ? 0 : ssum[t - 1];
    for (int i = 0; i < CH; i++) {
        int idx = base + i;
        if (idx <= N_NODESC) {
            int d = g_deg[idx];
            g_off[idx] = run;
            if (idx < N_NODESC) g_pos[idx] = run;
            run += d;
        }
    }
}

// ---------------- fill CSR (+ re-zero deg for next replay) ----------------
__global__ void fill_csr(const int* __restrict__ ei, const int* __restrict__ ea) {
    int e = blockIdx.x * blockDim.x + threadIdx.x;
    if (e <= N_NODESC) g_deg[e] = 0;
    if (e >= N_EDGESC) return;
    int src = __ldg(ei + e);
    int dst = __ldg(ei + N_EDGESC + e);
    int key = __ldg(ea + (size_t)e * 3 + 0) * 100
            + __ldg(ea + (size_t)e * 3 + 1) * 10
            + __ldg(ea + (size_t)e * 3 + 2);
    int slot = atomicAdd(&g_pos[dst], 1);
    g_csr[slot] = make_int2(src, key);
}

// ---------------- gather (bf16x2 SIMD, unroll 4; self term from g_hb) ----------------
__global__ void gather_mp(const __nv_bfloat16* __restrict__ bond) {
    int n = (int)(((size_t)blockIdx.x * blockDim.x + threadIdx.x) >> 5);
    if (n >= N_NODESC) return;
    int lane = threadIdx.x & 31;
    int fo = lane * 8;
    float acc[8];
    {
        uint4 hs = *(const uint4*)(g_hb + (size_t)n * DIM + fo);
        float2 v;
        v = __bfloat1622float2(*(const __nv_bfloat162*)&hs.x); acc[0] = v.x; acc[1] = v.y;
        v = __bfloat1622float2(*(const __nv_bfloat162*)&hs.y); acc[2] = v.x; acc[3] = v.y;
        v = __bfloat1622float2(*(const __nv_bfloat162*)&hs.z); acc[4] = v.x; acc[5] = v.y;
        v = __bfloat1622float2(*(const __nv_bfloat162*)&hs.w); acc[6] = v.x; acc[7] = v.y;
    }
    int p = g_off[n], pe = g_off[n + 1];
    if (p < pe && (p & 1)) {
        int2 sk = __ldg(&g_csr[p]);
        uint4 h = *(const uint4*)(g_hb + (size_t)sk.x * DIM + fo);
        uint4 b = *(const uint4*)(bond + (size_t)sk.y * DIM + fo);
        acc_edge(acc, h, b);
        p++;
    }
    for (; p + 4 <= pe; p += 4) {
        int4 e01 = *(const int4*)&g_csr[p];
        int4 e23 = *(const int4*)&g_csr[p + 2];
        uint4 h0 = *(const uint4*)(g_hb + (size_t)e01.x * DIM + fo);
        uint4 b0 = *(const uint4*)(bond + (size_t)e01.y * DIM + fo);
        uint4 h1 = *(const uint4*)(g_hb + (size_t)e01.z * DIM + fo);
        uint4 b1 = *(const uint4*)(bond + (size_t)e01.w * DIM + fo);
        uint4 h2 = *(const uint4*)(g_hb + (size_t)e23.x * DIM + fo);
        uint4 b2 = *(const uint4*)(bond + (size_t)e23.y * DIM + fo);
        uint4 h3 = *(const uint4*)(g_hb + (size_t)e23.z * DIM + fo);
        uint4 b3 = *(const uint4*)(bond + (size_t)e23.w * DIM + fo);
        acc_edge(acc, h0, b0);
        acc_edge(acc, h1, b1);
        acc_edge(acc, h2, b2);
        acc_edge(acc, h3, b3);
    }
    for (; p < pe; p++) {
        int2 sk = __ldg(&g_csr[p]);
        uint4 h = *(const uint4*)(g_hb + (size_t)sk.x * DIM + fo);
        uint4 b = *(const uint4*)(bond + (size_t)sk.y * DIM + fo);
        acc_edge(acc, h, b);
    }
    float* zd = g_z + (size_t)n * DIM + fo;
    *(float4*)(zd)     = make_float4(acc[0], acc[1], acc[2], acc[3]);
    *(float4*)(zd + 4) = make_float4(acc[4], acc[5], acc[6], acc[7]);
}

// ---------------- BN finalize ----------------
__global__ void finstats(const float* __restrict__ gamma, const float* __restrict__ beta,
                         int Dh, int off) {
    int c = blockIdx.x * 256 + threadIdx.x;
    if (c >= Dh) return;
    float inv_n = 1.0f / (float)N_NODESC;
    float mu = g_sum[off + c] * inv_n;
    float var = g_sq[off + c] * inv_n - mu * mu;
    float rs = rsqrtf(var + EPSC);
    float sc = rs * gamma[c];
    g_scale[c] = sc;
    g_shift[c] = beta[c] - mu * sc;
}

// ---------------- tf32 tensor-core GEMM 128x128x16 ----------------
// TRANSFORM: BN+ReLU on A-path. RELU: relu output. STATS>=0: fused col stats.
// STOREC: write fp32 C. BF16OUT: write bf16 C to g_hb. POOL: row-scatter sums to pool_out.
template <bool TRANSFORM, bool RELU, int STATS, bool STOREC, bool BF16OUT, bool POOL>
__global__ __launch_bounds__(256) void gemm_tc(
    const float* __restrict__ A, const float* __restrict__ B,
    const float* __restrict__ bias, float* __restrict__ C,
    const int* __restrict__ batch, float* __restrict__ pool_out,
    int M, int K, int Nc) {
    const int BM = 128, BN = 128, BK = 16;
    const int BKP = BK + 4;
    const int BNP = BN + 8;
    __shared__ float As[2][BM][BKP];
    __shared__ float Bs[2][BK][BNP];
    __shared__ int sbatch[BM];

    int tid = threadIdx.x;
    int lane = tid & 31;
    int wid = tid >> 5;
    int wm = wid & 1;
    int wn = wid >> 1;
    int bm = blockIdx.y * BM;
    int bn = blockIdx.x * BN;

    if (POOL && tid < BM) sbatch[tid] = (bm + tid < M) ? batch[bm + tid] : -1;

    int idx0 = tid, idx1 = tid + 256;
    int ar0 = idx0 >> 2, ak0 = (idx0 & 3) * 4;
    int ar1 = idx1 >> 2, ak1 = (idx1 & 3) * 4;
    int br0 = idx0 >> 5, bq0 = (idx0 & 31) * 4;
    int br1 = idx1 >> 5, bq1 = (idx1 & 31) * 4;
    bool aok0 = (bm + ar0) < M;
    bool aok1 = (bm + ar1) < M;

    float c[4][4][4];
#pragma unroll
    for (int mt = 0; mt < 4; mt++)
#pragma unroll
        for (int nt = 0; nt < 4; nt++)
#pragma unroll
            for (int r = 0; r < 4; r++) c[mt][nt][r] = 0.f;

    float4 a4s[2];

    auto ldg_a = [&](int k0) {
        a4s[0] = aok0 ? *(const float4*)(A + (size_t)(bm + ar0) * K + k0 + ak0)
                      : make_float4(0.f, 0.f, 0.f, 0.f);
        a4s[1] = aok1 ? *(const float4*)(A + (size_t)(bm + ar1) * K + k0 + ak1)
                      : make_float4(0.f, 0.f, 0.f, 0.f);
        if (TRANSFORM) {
#pragma unroll
            for (int t = 0; t < 2; t++) {
                int kb = k0 + ((t == 0) ? ak0 : ak1);
                float4& v = a4s[t];
                v.x = fmaxf(v.x * g_scale[kb + 0] + g_shift[kb + 0], 0.f);
                v.y = fmaxf(v.y * g_scale[kb + 1] + g_shift[kb + 1], 0.f);
                v.z = fmaxf(v.z * g_scale[kb + 2] + g_shift[kb + 2], 0.f);
                v.w = fmaxf(v.w * g_scale[kb + 3] + g_shift[kb + 3], 0.f);
            }
        }
    };
    auto sts_a = [&](int buf) {
        *(float4*)&As[buf][ar0][ak0] = make_float4(to_tf32(a4s[0].x), to_tf32(a4s[0].y),
                                                   to_tf32(a4s[0].z), to_tf32(a4s[0].w));
        *(float4*)&As[buf][ar1][ak1] = make_float4(to_tf32(a4s[1].x), to_tf32(a4s[1].y),
                                                   to_tf32(a4s[1].z), to_tf32(a4s[1].w));
    };
    auto ldb_async = [&](int buf, int k0) {
        cp_async16(&Bs[buf][br0][bq0], B + (size_t)(k0 + br0) * Nc + bn + bq0);
        cp_async16(&Bs[buf][br1][bq1], B + (size_t)(k0 + br1) * Nc + bn + bq1);
        cp_commit();
    };

    ldb_async(0, 0);
    ldg_a(0);
    sts_a(0);
    cp_wait0();
    __syncthreads();

    int nIter = K / BK;
    int lq = lane >> 2;
    int lr = lane & 3;
    for (int it = 0; it < nIter; it++) {
        int cur = it & 1, nxt = cur ^ 1;
        bool more = (it + 1 < nIter);
        if (more) {
            ldg_a((it + 1) * BK);
            ldb_async(nxt, (it + 1) * BK);
        }
#pragma unroll
        for (int ks = 0; ks < 2; ks++) {
            int k0 = ks * 8;
            uint32_t bf[4][2];
#pragma unroll
            for (int nt = 0; nt < 4; nt++) {
                int ncol = wn * 32 + nt * 8 + lq;
                bf[nt][0] = __float_as_uint(Bs[cur][k0 + lr][ncol]);
                bf[nt][1] = __float_as_uint(Bs[cur][k0 + 4 + lr][ncol]);
            }
#pragma unroll
            for (int mt = 0; mt < 4; mt++) {
                int mrow = wm * 64 + mt * 16 + lq;
                uint32_t af[4];
                af[0] = __float_as_uint(As[cur][mrow][k0 + lr]);
                af[1] = __float_as_uint(As[cur][mrow + 8][k0 + lr]);
                af[2] = __float_as_uint(As[cur][mrow][k0 + 4 + lr]);
                af[3] = __float_as_uint(As[cur][mrow + 8][k0 + 4 + lr]);
#pragma unroll
                for (int nt = 0; nt < 4; nt++) mma_tf32(c[mt][nt], af, bf[nt]);
            }
        }
        if (more) {
            sts_a(nxt);
            cp_wait0();
        }
        __syncthreads();
    }

    // ---------------- epilogue ----------------
    float2 bias2[4];
    int cbase[4];
#pragma unroll
    for (int nt = 0; nt < 4; nt++) {
        cbase[nt] = bn + wn * 32 + nt * 8 + lr * 2;
        bias2[nt] = *(const float2*)(bias + cbase[nt]);
    }

    float sx[4][2], qx[4][2];
    if (STATS >= 0) {
#pragma unroll
        for (int nt = 0; nt < 4; nt++) { sx[nt][0] = sx[nt][1] = 0.f; qx[nt][0] = qx[nt][1] = 0.f; }
    }

    // pool run-merge state (rows visited ascending: stride 8)
    float pl[4][2];
    int curb = -1;
    if (POOL) {
#pragma unroll
        for (int nt = 0; nt < 4; nt++) { pl[nt][0] = 0.f; pl[nt][1] = 0.f; }
    }

#pragma unroll
    for (int mt = 0; mt < 4; mt++) {
#pragma unroll
        for (int half = 0; half < 2; half++) {
            int rloc = wm * 64 + mt * 16 + lq + half * 8;
            int r = bm + rloc;
            if (r >= M) continue;
            float v[4][2];
#pragma unroll
            for (int nt = 0; nt < 4; nt++) {
                v[nt][0] = c[mt][nt][half * 2 + 0] + bias2[nt].x;
                v[nt][1] = c[mt][nt][half * 2 + 1] + bias2[nt].y;
                if (RELU) {
                    v[nt][0] = fmaxf(v[nt][0], 0.f);
                    v[nt][1] = fmaxf(v[nt][1], 0.f);
                }
                if (STATS >= 0) {
                    sx[nt][0] += v[nt][0]; sx[nt][1] += v[nt][1];
                    qx[nt][0] += v[nt][0] * v[nt][0]; qx[nt][1] += v[nt][1] * v[nt][1];
                }
            }
            if (STOREC) {
#pragma unroll
                for (int nt = 0; nt < 4; nt++)
                    *(float2*)(C + (size_t)r * Nc + cbase[nt]) = make_float2(v[nt][0], v[nt][1]);
            }
            if (BF16OUT) {
#pragma unroll
                for (int nt = 0; nt < 4; nt++)
                    *(__nv_bfloat162*)(g_hb + (size_t)r * DIM + cbase[nt]) =
                        __floats2bfloat162_rn(v[nt][0], v[nt][1]);
            }
            if (POOL) {
                int bg = sbatch[rloc];
                if (bg != curb) {
                    if (curb >= 0) {
#pragma unroll
                        for (int nt = 0; nt < 4; nt++) {
                            red_v2(pool_out + (size_t)curb * DIM + cbase[nt], pl[nt][0], pl[nt][1]);
                            pl[nt][0] = 0.f; pl[nt][1] = 0.f;
                        }
                    }
                    curb = bg;
                }
#pragma unroll
                for (int nt = 0; nt < 4; nt++) { pl[nt][0] += v[nt][0]; pl[nt][1] += v[nt][1]; }
            }
        }
    }
    if (POOL && curb >= 0) {
#pragma unroll
        for (int nt = 0; nt < 4; nt++)
            red_v2(pool_out + (size_t)curb * DIM + cbase[nt], pl[nt][0], pl[nt][1]);
    }

    if (STATS >= 0) {
#pragma unroll
        for (int nt = 0; nt < 4; nt++) {
#pragma unroll
            for (int h = 0; h < 2; h++) {
#pragma unroll
                for (int off = 4; off < 32; off <<= 1) {
                    sx[nt][h] += __shfl_xor_sync(0xffffffffu, sx[nt][h], off);
                    qx[nt][h] += __shfl_xor_sync(0xffffffffu, qx[nt][h], off);
                }
            }
        }
        if (lane < 4) {
#pragma unroll
            for (int nt = 0; nt < 4; nt++) {
                atomicAdd(&g_sum[STATS + cbase[nt] + 0], sx[nt][0]);
                atomicAdd(&g_sum[STATS + cbase[nt] + 1], sx[nt][1]);
                atomicAdd(&g_sq[STATS + cbase[nt] + 0], qx[nt][0]);
                atomicAdd(&g_sq[STATS + cbase[nt] + 1], qx[nt][1]);
            }
        }
    }
}

// ---------------- launch ----------------
extern "C" void kernel_launch(void* const* d_in, const int* in_sizes, int n_in,
                              void* d_out, int out_size) {
    const int* x      = (const int*)d_in[0];
    const int* ei     = (const int*)d_in[1];
    const int* ea     = (const int*)d_in[2];
    const int* batch  = (const int*)d_in[3];
    const float* atom = (const float*)d_in[4];
    const float* be1  = (const float*)d_in[5];
    const float* be2  = (const float*)d_in[6];
    const float* c1_w1 = (const float*)d_in[7];
    const float* c1_b1 = (const float*)d_in[8];
    const float* c1_g  = (const float*)d_in[9];
    const float* c1_be = (const float*)d_in[10];
    const float* c1_w2 = (const float*)d_in[11];
    const float* c1_b2 = (const float*)d_in[12];
    const float* c2_w1 = (const float*)d_in[13];
    const float* c2_b1 = (const float*)d_in[14];
    const float* c2_g  = (const float*)d_in[15];
    const float* c2_be = (const float*)d_in[16];
    const float* c2_w2 = (const float*)d_in[17];
    const float* c2_b2 = (const float*)d_in[18];
    float* out = (float*)d_out;

    float *zz, *yz, *wz;
    __nv_bfloat16 *bbz;
    cudaGetSymbolAddress((void**)&zz, g_z);
    cudaGetSymbolAddress((void**)&yz, g_y);
    cudaGetSymbolAddress((void**)&wz, g_w);
    cudaGetSymbolAddress((void**)&bbz, g_bondb);

    const int M = N_NODESC;
    const int eb = (N_EDGESC + 255) / 256;
    const int gb = (N_NODESC * 32 + 255) / 256;
    const int mtiles = (M + 127) / 128;
    dim3 gA(4, mtiles);   // Nc=512
    dim3 gB(2, mtiles);   // Nc=256

    // idx: mega(0) scan(1) fill(2) gather1(3) <- ncu samples idx 3
    mega_setup<<<41548, 256>>>(x, atom, be1, be2, c1_w1, c1_w2, c2_w1, c2_w2, ei, out);
    scan_offsets<<<1, 1024>>>();
    fill_csr<<<eb, 256>>>(ei, ea);

    // ---- conv1 ----
    gather_mp<<<gb, 256>>>(bbz);
    gemm_tc<false, false, 0, true, false, false><<<gA, 256>>>(zz, wz + 0, c1_b1, yz, nullptr, nullptr, M, 256, 512);
    finstats<<<2, 256>>>(c1_g, c1_be, 512, 0);
    gemm_tc<true, true, -1, false, true, false><<<gB, 256>>>(yz, wz + 131072, c1_b2, nullptr, nullptr, nullptr, M, 512, 256);

    // ---- conv2 ----
    gather_mp<<<gb, 256>>>(bbz + (size_t)1000 * DIM);
    gemm_tc<false, false, 512, true, false, false><<<gB, 256>>>(zz, wz + 262144, c2_b1, yz, nullptr, nullptr, M, 256, 256);
    finstats<<<1, 256>>>(c2_g, c2_be, 256, 512);
    gemm_tc<true, true, -1, false, false, true><<<gB, 256>>>(yz, wz + 327680, c2_b2, nullptr, batch, out, M, 256, 256);
}